// round 1
// baseline (speedup 1.0000x reference)
#include <cuda_runtime.h>
#include <cstdint>

#define BATCH  512
#define NELEC  32
#define NALL   36
#define NNUC   4
#define BASIS  32
#define KDIM   128
#define EDIM   128
#define HIDK   64
#define HIDO   128

// Scratch (device globals: allowed; no runtime allocation)
__device__ float g_xs[BATCH * NELEC * EDIM];   // (B,32,128)
__device__ float g_zs[BATCH * NALL * KDIM];    // (B,36,128)
__device__ float g_z [BATCH * NELEC * KDIM];   // (B,32,128)
__device__ float g_h2[BATCH * NELEC * HIDO];   // (B,32,128)

__device__ __forceinline__ float sspf(float x) {
    // softplus(x) - ln2, numerically stable, fast intrinsics (abs err ~1e-6)
    float e = __expf(-fabsf(x));
    float l = __logf(1.0f + e);
    return fmaxf(x, 0.0f) + l - 0.69314718055994530942f;
}

// ---------------------------------------------------------------------------
// init kernels
// ---------------------------------------------------------------------------
__global__ void init_xs_kernel(const float* __restrict__ emb_e, float* __restrict__ xs) {
    int idx = blockIdx.x * blockDim.x + threadIdx.x;
    if (idx < BATCH * NELEC * EDIM) {
        xs[idx] = emb_e[idx & (NELEC * EDIM - 1)];  // broadcast over batch
    }
}

__global__ void init_zsnuc_kernel(const float* __restrict__ emb_n, float* __restrict__ zs) {
    int idx = blockIdx.x * blockDim.x + threadIdx.x;
    if (idx < BATCH * NNUC * KDIM) {
        int d = idx & 127;
        int m = (idx >> 7) & 3;
        int b = idx >> 9;
        zs[(b * NALL + NELEC + m) * KDIM + d] = emb_n[m * KDIM + d];
    }
}

// ---------------------------------------------------------------------------
// Generic batched linear: out[b,e,n] = (act?)(bias[n] + sum_d in[b,e,d]*W[n,d]) (+ res)
// Grid = BATCH blocks, 256 threads. 32 rows x 128 cols per block, K=128.
// ---------------------------------------------------------------------------
template <bool USE_BIAS, bool ACT, bool RES>
__global__ __launch_bounds__(256) void linear_kernel(
    const float* __restrict__ in, const float* __restrict__ W,
    const float* __restrict__ bias, const float* __restrict__ res,
    float* __restrict__ out, int out_bstride)
{
    __shared__ __align__(16) float in_s[32][128];
    __shared__ __align__(16) float Wt_s[32][132];  // pad 132: conflict-free col reads

    int b = blockIdx.x;
    int tid = threadIdx.x;
    const float* inb = in + b * 4096;

    // load full input tile (32x128) once
#pragma unroll
    for (int q = 0; q < 4; q++) {
        int i4 = tid + q * 256;
        ((float4*)in_s)[i4] = ((const float4*)inb)[i4];
    }

    int tx = tid & 31, ty = tid >> 5;
    int n0 = tx * 4, e0 = ty * 4;
    float acc[4][4] = {};

    for (int k0 = 0; k0 < 128; k0 += 32) {
        __syncthreads();  // protect Wt_s reuse (also orders in_s load on first pass)
#pragma unroll
        for (int q = 0; q < 16; q++) {
            int lin = tid + q * 256;
            int n = lin >> 5, dd = lin & 31;
            Wt_s[dd][n] = W[n * 128 + k0 + dd];
        }
        __syncthreads();
#pragma unroll
        for (int dd = 0; dd < 32; dd++) {
            float4 w = *(const float4*)&Wt_s[dd][n0];
#pragma unroll
            for (int i = 0; i < 4; i++) {
                float a = in_s[e0 + i][k0 + dd];  // broadcast across lanes
                acc[i][0] = fmaf(a, w.x, acc[i][0]);
                acc[i][1] = fmaf(a, w.y, acc[i][1]);
                acc[i][2] = fmaf(a, w.z, acc[i][2]);
                acc[i][3] = fmaf(a, w.w, acc[i][3]);
            }
        }
    }

    float4 bi = make_float4(0.f, 0.f, 0.f, 0.f);
    if (USE_BIAS) bi = *(const float4*)&bias[n0];
#pragma unroll
    for (int i = 0; i < 4; i++) {
        float4 v = make_float4(acc[i][0] + bi.x, acc[i][1] + bi.y,
                               acc[i][2] + bi.z, acc[i][3] + bi.w);
        if (ACT) { v.x = sspf(v.x); v.y = sspf(v.y); v.z = sspf(v.z); v.w = sspf(v.w); }
        if (RES) {
            float4 r = *(const float4*)&res[b * 4096 + (e0 + i) * 128 + n0];
            v.x += r.x; v.y += r.y; v.z += r.z; v.w += r.w;
        }
        *(float4*)&out[b * out_bstride + (e0 + i) * 128 + n0] = v;
    }
}

// ---------------------------------------------------------------------------
// Fused pair conv: for each (b,e): z[b,e,:] = sum_j (W2·ssp(W1·db + b1) + b2) * zs[b, c_j(e,j), :]
// Grid = BATCH*8 blocks (4 electrons each, processed as 2 pairs), 128 threads.
// W1 row (32f) and W2 row (64f) register-stationary per thread.
// ---------------------------------------------------------------------------
__global__ __launch_bounds__(128) void pairconv_kernel(
    const float* __restrict__ dists,   // (B,32,36,32)
    const float* __restrict__ w1,      // (64,32)  for this t
    const float* __restrict__ b1v,     // (64)
    const float* __restrict__ w2,      // (128,64)
    const float* __restrict__ b2v,     // (128)
    const float* __restrict__ zs,      // (B,36,128)
    float* __restrict__ z)             // (B,32,128)
{
    __shared__ __align__(16) float db_s[2][35][32];
    __shared__ __align__(16) float h_s[2][2][64];  // [parity][electron-half][h]

    int tid = threadIdx.x;
    int blk = blockIdx.x;
    int b = blk >> 3, eg = blk & 7;
    int k = tid;            // output channel 0..127 (stage 2)
    int hh = tid & 63;      // hidden unit    0..63  (stage 1)
    int eh = tid >> 6;      // electron half  0..1   (stage 1)

    float4 w1r[8], w2r[16];
#pragma unroll
    for (int q = 0; q < 8; q++)  w1r[q] = ((const float4*)(w1 + hh * 32))[q];
#pragma unroll
    for (int q = 0; q < 16; q++) w2r[q] = ((const float4*)(w2 + k * 64))[q];
    float b1k = b1v[hh];
    float b2k = b2v[k];
    const float* zrow = zs + b * (NALL * KDIM);

    for (int ep = 0; ep < 2; ep++) {
        int e0 = eg * 4 + ep * 2;  // pair: electrons e0, e0+1

        // cooperative gather of db for both electrons (skip j==e row)
#pragma unroll
        for (int q = 0; q < 5; q++) {
            int idx = tid + q * 128;      // float4 index, 0..559
            if (idx < 560) {
                int ehl = idx / 280;
                int rem = idx - ehl * 280;
                int jj = rem >> 3, i4 = rem & 7;
                int e = e0 + ehl;
                int j = jj + (jj >= e ? 1 : 0);
                ((float4*)db_s)[idx] =
                    ((const float4*)dists)[((b * NELEC + e) * NALL + j) * 8 + i4];
            }
        }
        __syncthreads();

        float za = 0.f, zb = 0.f;
        for (int jj = 0; jj < 35; jj++) {
            // prefetch zj (hidden behind stage1+bar+stage2)
            int jA = jj + (jj >= e0 ? 1 : 0);
            int jB = jj + (jj >= e0 + 1 ? 1 : 0);
            float zja = zrow[jA * 128 + k];
            float zjb = zrow[jB * 128 + k];

            // stage 1: h = ssp(W1 . db + b1); threads split across the 2 electrons
            const float4* dv = (const float4*)db_s[eh][jj];
            float ha = b1k;
#pragma unroll
            for (int q = 0; q < 8; q++) {
                float4 d4 = dv[q];
                ha = fmaf(w1r[q].x, d4.x, ha);
                ha = fmaf(w1r[q].y, d4.y, ha);
                ha = fmaf(w1r[q].z, d4.z, ha);
                ha = fmaf(w1r[q].w, d4.w, ha);
            }
            int par = jj & 1;
            h_s[par][eh][hh] = sspf(ha);
            __syncthreads();  // single bar per j: h double-buffered on parity

            // stage 2: Ws = W2 . h + b2 for BOTH electrons; accumulate z
            float wsa = b2k, wsb = b2k;
            const float4* hA = (const float4*)h_s[par][0];
            const float4* hB = (const float4*)h_s[par][1];
#pragma unroll
            for (int q = 0; q < 16; q++) {
                float4 a4 = hA[q], c4 = hB[q], w = w2r[q];
                wsa = fmaf(w.x, a4.x, wsa); wsb = fmaf(w.x, c4.x, wsb);
                wsa = fmaf(w.y, a4.y, wsa); wsb = fmaf(w.y, c4.y, wsb);
                wsa = fmaf(w.z, a4.z, wsa); wsb = fmaf(w.z, c4.z, wsb);
                wsa = fmaf(w.w, a4.w, wsa); wsb = fmaf(w.w, c4.w, wsb);
            }
            za = fmaf(wsa, zja, za);
            zb = fmaf(wsb, zjb, zb);
        }
        z[(b * NELEC + e0) * 128 + k]     = za;
        z[(b * NELEC + e0 + 1) * 128 + k] = zb;
        __syncthreads();  // protect db_s before next pair
    }
}

// ---------------------------------------------------------------------------
// launch
// ---------------------------------------------------------------------------
extern "C" void kernel_launch(void* const* d_in, const int* in_sizes, int n_in,
                              void* d_out, int out_size)
{
    const float* dists = (const float*)d_in[0];   // (512,32,36,32)
    const float* emb_e = (const float*)d_in[1];   // (32,128)
    const float* emb_n = (const float*)d_in[2];   // (4,128)
    const float* w1    = (const float*)d_in[3];   // (3,64,32)
    const float* b1    = (const float*)d_in[4];   // (3,64)
    const float* w2    = (const float*)d_in[5];   // (3,128,64)
    const float* b2    = (const float*)d_in[6];   // (3,128)
    const float* win   = (const float*)d_in[7];   // (3,128,128)
    const float* wo1   = (const float*)d_in[8];   // (3,128,128)
    const float* bo1   = (const float*)d_in[9];   // (3,128)
    const float* wo2   = (const float*)d_in[10];  // (3,128,128)
    const float* bo2   = (const float*)d_in[11];  // (3,128)
    float* out = (float*)d_out;

    float *xs, *zsv, *zv, *h2;
    cudaGetSymbolAddress((void**)&xs,  g_xs);
    cudaGetSymbolAddress((void**)&zsv, g_zs);
    cudaGetSymbolAddress((void**)&zv,  g_z);
    cudaGetSymbolAddress((void**)&h2,  g_h2);

    init_xs_kernel<<<(BATCH * NELEC * EDIM + 255) / 256, 256>>>(emb_e, xs);
    init_zsnuc_kernel<<<(BATCH * NNUC * KDIM + 255) / 256, 256>>>(emb_n, zsv);

    for (int t = 0; t < 3; t++) {
        // zs[:, :32] = xs @ Win^T   (nuc rows written once at init)
        linear_kernel<false, false, false><<<BATCH, 256>>>(
            xs, win + t * KDIM * EDIM, nullptr, nullptr, zsv, NALL * KDIM);

        // z = fused pair conv
        pairconv_kernel<<<BATCH * 8, 128>>>(
            dists, w1 + t * HIDK * BASIS, b1 + t * HIDK,
            w2 + t * KDIM * HIDK, b2 + t * KDIM, zsv, zv);

        // h2 = ssp(z @ Wo1^T + bo1)
        linear_kernel<true, true, false><<<BATCH, 256>>>(
            zv, wo1 + t * HIDO * KDIM, bo1 + t * HIDO, nullptr, h2, NELEC * KDIM);

        // xs = xs + h2 @ Wo2^T + bo2   (last iter writes d_out directly)
        float* dst = (t == 2) ? out : xs;
        linear_kernel<true, false, true><<<BATCH, 256>>>(
            h2, wo2 + t * EDIM * HIDO, bo2 + t * EDIM, xs, dst, NELEC * EDIM);
    }
}

// round 3
// speedup vs baseline: 1.1239x; 1.1239x over previous
#include <cuda_runtime.h>
#include <cstdint>

#define BATCH  512
#define NELEC  32
#define NALL   36
#define NNUC   4
#define BASIS  32
#define KDIM   128
#define EDIM   128
#define HIDK   64
#define HIDO   128

// Scratch (device globals: allowed; no runtime allocation)
__device__ float g_xs[BATCH * NELEC * EDIM];   // (B,32,128)
__device__ float g_zs[BATCH * NALL * KDIM];    // (B,36,128)
__device__ float g_z [BATCH * NELEC * KDIM];   // (B,32,128)
__device__ float g_h2[BATCH * NELEC * HIDO];   // (B,32,128)

// Packed fp32x2 FMA (sm_100+; ptxas never emits FFMA2 from C++)
#define FMA_F32X2(d, a, b, c) \
    asm("fma.rn.f32x2 %0, %1, %2, %3;" : "=l"(d) : "l"(a), "l"(b), "l"(c))

__device__ __forceinline__ float f2lo(unsigned long long v) {
    return __uint_as_float((unsigned)v);
}
__device__ __forceinline__ float f2hi(unsigned long long v) {
    return __uint_as_float((unsigned)(v >> 32));
}

__device__ __forceinline__ float sspf(float x) {
    // softplus(x) - ln2, numerically stable, fast intrinsics
    float e = __expf(-fabsf(x));
    float l = __logf(1.0f + e);
    return fmaxf(x, 0.0f) + l - 0.69314718055994530942f;
}

// ---------------------------------------------------------------------------
// init kernels
// ---------------------------------------------------------------------------
__global__ void init_xs_kernel(const float* __restrict__ emb_e, float* __restrict__ xs) {
    int idx = blockIdx.x * blockDim.x + threadIdx.x;
    if (idx < BATCH * NELEC * EDIM) {
        xs[idx] = emb_e[idx & (NELEC * EDIM - 1)];
    }
}

__global__ void init_zsnuc_kernel(const float* __restrict__ emb_n, float* __restrict__ zs) {
    int idx = blockIdx.x * blockDim.x + threadIdx.x;
    if (idx < BATCH * NNUC * KDIM) {
        int d = idx & 127;
        int m = (idx >> 7) & 3;
        int b = idx >> 9;
        zs[(b * NALL + NELEC + m) * KDIM + d] = emb_n[m * KDIM + d];
    }
}

// ---------------------------------------------------------------------------
// Linear: out[b,e,n] = (act?)(bias[n] + sum_d in[b,e,d]*W[n,d]) (+ res)
// FFMA2 packed along reduction dim d (full d=0..127: q=0..31, 4 floats/q).
// Grid = BATCH, 256 threads. Thread (tx,ty): electrons e0=4*ty..+3,
// channels n = tx + 32m (m=0..3). Ws_s pad 132 keeps LDS.128 conflict-free.
// ---------------------------------------------------------------------------
template <bool USE_BIAS, bool ACT, bool RES>
__global__ __launch_bounds__(256) void linear_kernel(
    const float* __restrict__ in, const float* __restrict__ W,
    const float* __restrict__ bias, const float* __restrict__ res,
    float* __restrict__ out, int out_bstride)
{
    __shared__ __align__(16) float in_s[32][128];
    __shared__ __align__(16) float Ws_s[128][132];

    int b = blockIdx.x;
    int tid = threadIdx.x;
    const float* inb = in + b * 4096;

#pragma unroll
    for (int q = 0; q < 4; q++) {
        int i4 = tid + q * 256;
        ((float4*)in_s)[i4] = ((const float4*)inb)[i4];
    }
#pragma unroll
    for (int q = 0; q < 16; q++) {
        int idx4 = tid + q * 256;
        int n = idx4 >> 5, d4 = idx4 & 31;
        *(float4*)&Ws_s[n][d4 * 4] = *(const float4*)&W[n * 128 + d4 * 4];
    }
    __syncthreads();

    int tx = tid & 31, ty = tid >> 5;
    int e0 = ty * 4;

    unsigned long long acc[4][4];
#pragma unroll
    for (int i = 0; i < 4; i++)
#pragma unroll
        for (int m = 0; m < 4; m++) acc[i][m] = 0ull;

#pragma unroll 8
    for (int q = 0; q < 32; q++) {            // FULL reduction: 32 * 4 floats = 128
        ulonglong2 a2[4], wr[4];
#pragma unroll
        for (int i = 0; i < 4; i++)
            a2[i] = *(const ulonglong2*)&in_s[e0 + i][q * 4];
#pragma unroll
        for (int m = 0; m < 4; m++)
            wr[m] = *(const ulonglong2*)&Ws_s[tx + 32 * m][q * 4];
#pragma unroll
        for (int i = 0; i < 4; i++) {
#pragma unroll
            for (int m = 0; m < 4; m++) {
                FMA_F32X2(acc[i][m], wr[m].x, a2[i].x, acc[i][m]);
                FMA_F32X2(acc[i][m], wr[m].y, a2[i].y, acc[i][m]);
            }
        }
    }

    float bi[4] = {0.f, 0.f, 0.f, 0.f};
    if (USE_BIAS) {
#pragma unroll
        for (int m = 0; m < 4; m++) bi[m] = bias[tx + 32 * m];
    }
#pragma unroll
    for (int i = 0; i < 4; i++) {
#pragma unroll
        for (int m = 0; m < 4; m++) {
            int n = tx + 32 * m;
            float v = f2lo(acc[i][m]) + f2hi(acc[i][m]) + bi[m];
            if (ACT) v = sspf(v);
            if (RES) v += res[b * 4096 + (e0 + i) * 128 + n];
            out[b * out_bstride + (e0 + i) * 128 + n] = v;
        }
    }
}

// ---------------------------------------------------------------------------
// Fused pair conv (FFMA2): z[b,e,:] = sum_j (W2.ssp(W1.db + b1) + b2) * zs[b,c_j,:]
// Grid = BATCH*8 blocks, 128 threads, 4 electrons per CTA, 1 barrier per j
// (parity double-buffered h_s).
// ---------------------------------------------------------------------------
__global__ __launch_bounds__(128, 4) void pairconv_kernel(
    const float* __restrict__ dists,   // (B,32,36,32)
    const float* __restrict__ w1,      // (64,32)
    const float* __restrict__ b1v,     // (64)
    const float* __restrict__ w2,      // (128,64)
    const float* __restrict__ b2v,     // (128)
    const float* __restrict__ zs,      // (B,36,128)
    float* __restrict__ z)             // (B,32,128)
{
    __shared__ __align__(16) float db_s[4][35][32];
    __shared__ __align__(16) float h_s[2][4][64];   // [parity][electron][h]

    int tid = threadIdx.x;
    int b = blockIdx.x >> 3, eg = blockIdx.x & 7;
    int e0 = eg * 4;
    int k = tid;           // channel (stage 2)
    int hh = tid & 63;     // hidden unit (stage 1)
    int g = tid >> 6;      // stage-1 electron group: handles e0+2g, e0+2g+1

    // register-stationary packed weights (packed along reduction dim)
    unsigned long long w1u[16], w2u[32];
    {
        const ulonglong2* p1 = (const ulonglong2*)(w1 + hh * 32);
#pragma unroll
        for (int q = 0; q < 8; q++) { ulonglong2 v = p1[q]; w1u[2*q] = v.x; w1u[2*q+1] = v.y; }
        const ulonglong2* p2 = (const ulonglong2*)(w2 + k * 64);
#pragma unroll
        for (int q = 0; q < 16; q++) { ulonglong2 v = p2[q]; w2u[2*q] = v.x; w2u[2*q+1] = v.y; }
    }
    float b1k = b1v[hh];
    float b2k = b2v[k];
    const float* zrow = zs + b * (NALL * KDIM);

    // cooperative gather of db for 4 electrons (skip j==e row)
#pragma unroll
    for (int q = 0; q < 9; q++) {
        int idx = tid + q * 128;   // float4 index, 0..1119
        if (idx < 1120) {
            int e = idx / 280;
            int rem = idx - e * 280;
            int jj = rem >> 3, i4 = rem & 7;
            int j = jj + (jj >= e0 + e ? 1 : 0);
            *(float4*)&db_s[e][jj][i4 * 4] =
                *(const float4*)&dists[(((b * NELEC + e0 + e) * NALL + j) << 5) + i4 * 4];
        }
    }
    __syncthreads();

    float za[4] = {0.f, 0.f, 0.f, 0.f};

    for (int jj = 0; jj < 35; jj++) {
        int par = jj & 1;

        // prefetch zj (hidden behind stage1 + bar + stage2)
        float zj[4];
#pragma unroll
        for (int e = 0; e < 4; e++) {
            int j = jj + (jj >= e0 + e ? 1 : 0);
            zj[e] = zrow[j * 128 + k];
        }

        // stage 1: h = ssp(W1 . db + b1) for this thread's 2 electrons
#pragma unroll
        for (int s = 0; s < 2; s++) {
            int e = 2 * g + s;
            const ulonglong2* dv = (const ulonglong2*)db_s[e][jj];
            unsigned long long a0 = 0ull, a1 = 0ull;
#pragma unroll
            for (int q = 0; q < 8; q++) {
                ulonglong2 d2 = dv[q];
                FMA_F32X2(a0, w1u[2*q],     d2.x, a0);
                FMA_F32X2(a1, w1u[2*q + 1], d2.y, a1);
            }
            float hs = f2lo(a0) + f2hi(a0) + f2lo(a1) + f2hi(a1) + b1k;
            h_s[par][e][hh] = sspf(hs);
        }
        __syncthreads();   // single barrier per j (parity double buffer)

        // stage 2: Ws = W2 . h + b2 for all 4 electrons; accumulate z
#pragma unroll
        for (int e = 0; e < 4; e++) {
            const ulonglong2* hv = (const ulonglong2*)h_s[par][e];
            unsigned long long a0 = 0ull, a1 = 0ull;
#pragma unroll
            for (int q = 0; q < 16; q++) {
                ulonglong2 h2v = hv[q];
                FMA_F32X2(a0, w2u[2*q],     h2v.x, a0);
                FMA_F32X2(a1, w2u[2*q + 1], h2v.y, a1);
            }
            float ws = f2lo(a0) + f2hi(a0) + f2lo(a1) + f2hi(a1) + b2k;
            za[e] = fmaf(ws, zj[e], za[e]);
        }
    }

#pragma unroll
    for (int e = 0; e < 4; e++)
        z[((b * NELEC + e0 + e) << 7) + k] = za[e];
}

// ---------------------------------------------------------------------------
// launch
// ---------------------------------------------------------------------------
extern "C" void kernel_launch(void* const* d_in, const int* in_sizes, int n_in,
                              void* d_out, int out_size)
{
    const float* dists = (const float*)d_in[0];   // (512,32,36,32)
    const float* emb_e = (const float*)d_in[1];   // (32,128)
    const float* emb_n = (const float*)d_in[2];   // (4,128)
    const float* w1    = (const float*)d_in[3];   // (3,64,32)
    const float* b1    = (const float*)d_in[4];   // (3,64)
    const float* w2    = (const float*)d_in[5];   // (3,128,64)
    const float* b2    = (const float*)d_in[6];   // (3,128)
    const float* win   = (const float*)d_in[7];   // (3,128,128)
    const float* wo1   = (const float*)d_in[8];   // (3,128,128)
    const float* bo1   = (const float*)d_in[9];   // (3,128)
    const float* wo2   = (const float*)d_in[10];  // (3,128,128)
    const float* bo2   = (const float*)d_in[11];  // (3,128)
    float* out = (float*)d_out;

    float *xs, *zsv, *zv, *h2;
    cudaGetSymbolAddress((void**)&xs,  g_xs);
    cudaGetSymbolAddress((void**)&zsv, g_zs);
    cudaGetSymbolAddress((void**)&zv,  g_z);
    cudaGetSymbolAddress((void**)&h2,  g_h2);

    init_xs_kernel<<<(BATCH * NELEC * EDIM + 255) / 256, 256>>>(emb_e, xs);
    init_zsnuc_kernel<<<(BATCH * NNUC * KDIM + 255) / 256, 256>>>(emb_n, zsv);

    for (int t = 0; t < 3; t++) {
        // zs[:, :32] = xs @ Win^T   (nuc rows written once at init)
        linear_kernel<false, false, false><<<BATCH, 256>>>(
            xs, win + t * KDIM * EDIM, nullptr, nullptr, zsv, NALL * KDIM);

        // z = fused pair conv
        pairconv_kernel<<<BATCH * 8, 128>>>(
            dists, w1 + t * HIDK * BASIS, b1 + t * HIDK,
            w2 + t * KDIM * HIDK, b2 + t * KDIM, zsv, zv);

        // h2 = ssp(z @ Wo1^T + bo1)
        linear_kernel<true, true, false><<<BATCH, 256>>>(
            zv, wo1 + t * HIDO * KDIM, bo1 + t * HIDO, nullptr, h2, NELEC * KDIM);

        // xs = xs + h2 @ Wo2^T + bo2   (last iter writes d_out directly)
        float* dst = (t == 2) ? out : xs;
        linear_kernel<true, false, true><<<BATCH, 256>>>(
            h2, wo2 + t * EDIM * HIDO, bo2 + t * EDIM, xs, dst, NELEC * EDIM);
    }
}

// round 4
// speedup vs baseline: 1.3845x; 1.2319x over previous
#include <cuda_runtime.h>
#include <cstdint>

#define BATCH  512
#define NELEC  32
#define NALL   36
#define NNUC   4
#define BASIS  32
#define KDIM   128
#define EDIM   128
#define HIDK   64
#define HIDO   128

// Scratch (device globals)
__device__ float g_xs[BATCH * NELEC * EDIM];
__device__ float g_zs[BATCH * NALL * KDIM];
__device__ float g_z [BATCH * NELEC * KDIM];
__device__ float g_h2[BATCH * NELEC * HIDO];

// Packed fp32x2 FMA (for the fp32 linear layers)
#define FMA_F32X2(d, a, b, c) \
    asm("fma.rn.f32x2 %0, %1, %2, %3;" : "=l"(d) : "l"(a), "l"(b), "l"(c))

__device__ __forceinline__ float f2lo(unsigned long long v) { return __uint_as_float((unsigned)v); }
__device__ __forceinline__ float f2hi(unsigned long long v) { return __uint_as_float((unsigned)(v >> 32)); }

__device__ __forceinline__ float sspf(float x) {
    float e = __expf(-fabsf(x));
    float l = __logf(1.0f + e);
    return fmaxf(x, 0.0f) + l - 0.69314718055994530942f;
}

// ---------------- bf16 MMA helpers ----------------
__device__ __forceinline__ void mma_bf16(float* c, const unsigned* a, const unsigned* b) {
    asm volatile("mma.sync.aligned.m16n8k16.row.col.f32.bf16.bf16.f32 "
        "{%0,%1,%2,%3}, {%4,%5,%6,%7}, {%8,%9}, {%0,%1,%2,%3};"
        : "+f"(c[0]), "+f"(c[1]), "+f"(c[2]), "+f"(c[3])
        : "r"(a[0]), "r"(a[1]), "r"(a[2]), "r"(a[3]), "r"(b[0]), "r"(b[1]));
}

// pack two fp32 into bf16x2 (f0 -> low half / first k, f1 -> high half / second k)
__device__ __forceinline__ unsigned pack_bf16(float f0, float f1) {
    unsigned r;
    asm("cvt.rn.bf16x2.f32 %0, %1, %2;" : "=r"(r) : "f"(f1), "f"(f0));
    return r;
}
// hi/lo split: f = bf16(f) + bf16(f - bf16(f)) (approx; lo rounded)
__device__ __forceinline__ void split2(float f0, float f1, unsigned &hi, unsigned &lo) {
    hi = pack_bf16(f0, f1);
    float h0 = __uint_as_float(hi << 16);
    float h1 = __uint_as_float(hi & 0xFFFF0000u);
    lo = pack_bf16(f0 - h0, f1 - h1);
}

// ---------------------------------------------------------------------------
// init kernels
// ---------------------------------------------------------------------------
__global__ void init_xs_kernel(const float* __restrict__ emb_e, float* __restrict__ xs) {
    int idx = blockIdx.x * blockDim.x + threadIdx.x;
    if (idx < BATCH * NELEC * EDIM) xs[idx] = emb_e[idx & (NELEC * EDIM - 1)];
}

__global__ void init_zsnuc_kernel(const float* __restrict__ emb_n, float* __restrict__ zs) {
    int idx = blockIdx.x * blockDim.x + threadIdx.x;
    if (idx < BATCH * NNUC * KDIM) {
        int d = idx & 127;
        int m = (idx >> 7) & 3;
        int b = idx >> 9;
        zs[(b * NALL + NELEC + m) * KDIM + d] = emb_n[m * KDIM + d];
    }
}

// ---------------------------------------------------------------------------
// fp32 FFMA2 linear (unchanged from R3 — passing)
// ---------------------------------------------------------------------------
template <bool USE_BIAS, bool ACT, bool RES>
__global__ __launch_bounds__(256) void linear_kernel(
    const float* __restrict__ in, const float* __restrict__ W,
    const float* __restrict__ bias, const float* __restrict__ res,
    float* __restrict__ out, int out_bstride)
{
    __shared__ __align__(16) float in_s[32][128];
    __shared__ __align__(16) float Ws_s[128][132];

    int b = blockIdx.x;
    int tid = threadIdx.x;
    const float* inb = in + b * 4096;

#pragma unroll
    for (int q = 0; q < 4; q++) {
        int i4 = tid + q * 256;
        ((float4*)in_s)[i4] = ((const float4*)inb)[i4];
    }
#pragma unroll
    for (int q = 0; q < 16; q++) {
        int idx4 = tid + q * 256;
        int n = idx4 >> 5, d4 = idx4 & 31;
        *(float4*)&Ws_s[n][d4 * 4] = *(const float4*)&W[n * 128 + d4 * 4];
    }
    __syncthreads();

    int tx = tid & 31, ty = tid >> 5;
    int e0 = ty * 4;

    unsigned long long acc[4][4];
#pragma unroll
    for (int i = 0; i < 4; i++)
#pragma unroll
        for (int m = 0; m < 4; m++) acc[i][m] = 0ull;

#pragma unroll 8
    for (int q = 0; q < 32; q++) {
        ulonglong2 a2[4], wr[4];
#pragma unroll
        for (int i = 0; i < 4; i++)
            a2[i] = *(const ulonglong2*)&in_s[e0 + i][q * 4];
#pragma unroll
        for (int m = 0; m < 4; m++)
            wr[m] = *(const ulonglong2*)&Ws_s[tx + 32 * m][q * 4];
#pragma unroll
        for (int i = 0; i < 4; i++) {
#pragma unroll
            for (int m = 0; m < 4; m++) {
                FMA_F32X2(acc[i][m], wr[m].x, a2[i].x, acc[i][m]);
                FMA_F32X2(acc[i][m], wr[m].y, a2[i].y, acc[i][m]);
            }
        }
    }

    float bi[4] = {0.f, 0.f, 0.f, 0.f};
    if (USE_BIAS) {
#pragma unroll
        for (int m = 0; m < 4; m++) bi[m] = bias[tx + 32 * m];
    }
#pragma unroll
    for (int i = 0; i < 4; i++) {
#pragma unroll
        for (int m = 0; m < 4; m++) {
            int n = tx + 32 * m;
            float v = f2lo(acc[i][m]) + f2hi(acc[i][m]) + bi[m];
            if (ACT) v = sspf(v);
            if (RES) v += res[b * 4096 + (e0 + i) * 128 + n];
            out[b * out_bstride + (e0 + i) * 128 + n] = v;
        }
    }
}

// ---------------------------------------------------------------------------
// Pair conv via mma.sync bf16x3.
// CTA = (b, 8 electrons): M = 8*36 = 288 rows (j==e included, zeroed in epilogue).
// 9 warps x 2 m16-tiles. GEMM1: [288,32]x[32,64]; ssp; GEMM2: [288,64]x[64,128];
// epilogue: z[e,k] += (Ws + b2)[row,k] * zs[b,j,k] (row=(e,j)), shfl-reduced.
// ---------------------------------------------------------------------------
__global__ __launch_bounds__(288) void pairconv_mma_kernel(
    const float* __restrict__ dists,   // (B,32,36,32)
    const float* __restrict__ w1,      // (64,32)
    const float* __restrict__ b1g,     // (64)
    const float* __restrict__ w2,      // (128,64)
    const float* __restrict__ b2g,     // (128)
    const float* __restrict__ zs,      // (B,36,128)
    float* __restrict__ z)             // (B,32,128)
{
    __shared__ unsigned W1p[2][16][72];    // [hi/lo][k/2][n]  (pad 72: conflict-free)
    __shared__ unsigned W2p[2][32][136];   // [hi/lo][k/2][n]  (pad 136)
    __shared__ float z_s[8][128];

    int tid = threadIdx.x;
    int b = blockIdx.x >> 2;
    int e0g = (blockIdx.x & 3) * 8;
    int wid = tid >> 5, lane = tid & 31;
    int g = lane >> 2, t = lane & 3;

    // pre-split weights into smem (packed bf16x2 along k)
    for (int idx = tid; idx < 16 * 64; idx += 288) {
        int kk = idx >> 6, n = idx & 63;
        unsigned hi, lo;
        split2(w1[n * 32 + 2 * kk], w1[n * 32 + 2 * kk + 1], hi, lo);
        W1p[0][kk][n] = hi; W1p[1][kk][n] = lo;
    }
    for (int idx = tid; idx < 32 * 128; idx += 288) {
        int kk = idx >> 7, n = idx & 127;
        unsigned hi, lo;
        split2(w2[n * 64 + 2 * kk], w2[n * 64 + 2 * kk + 1], hi, lo);
        W2p[0][kk][n] = hi; W2p[1][kk][n] = lo;
    }
    for (int idx = tid; idx < 1024; idx += 288) ((float*)z_s)[idx] = 0.f;
    __syncthreads();

    // b1 values for this lane's columns (cols 2t,2t+1 of each n-tile)
    float b1r[16];
#pragma unroll
    for (int nt = 0; nt < 8; nt++) {
        float2 v = *(const float2*)&b1g[nt * 8 + 2 * t];
        b1r[2 * nt] = v.x; b1r[2 * nt + 1] = v.y;
    }

    const float* drow = dists + ((long)(b * 32 + e0g) * 36) * 32;
    const float* zrow = zs + b * (36 * 128);

#pragma unroll
    for (int i = 0; i < 2; i++) {
        int mb = wid * 32 + i * 16;     // m-tile base row (0..272)

        // ---------------- GEMM1: C1[16,64] = db x W1^T ----------------
        float c1[8][4];
#pragma unroll
        for (int nt = 0; nt < 8; nt++)
#pragma unroll
            for (int q = 0; q < 4; q++) c1[nt][q] = 0.f;

        int r0 = mb + g, r1 = r0 + 8;
        int ea = r0 / 36, ja = r0 - 36 * ea;
        int eb = r1 / 36, jb = r1 - 36 * eb;

#pragma unroll
        for (int kt = 0; kt < 2; kt++) {
            int col = 16 * kt + 2 * t;
            float2 v00 = *(const float2*)&drow[(ea * 36 + ja) * 32 + col];
            float2 v10 = *(const float2*)&drow[(eb * 36 + jb) * 32 + col];
            float2 v01 = *(const float2*)&drow[(ea * 36 + ja) * 32 + col + 8];
            float2 v11 = *(const float2*)&drow[(eb * 36 + jb) * 32 + col + 8];
            unsigned ah[4], al[4];
            split2(v00.x, v00.y, ah[0], al[0]);
            split2(v10.x, v10.y, ah[1], al[1]);
            split2(v01.x, v01.y, ah[2], al[2]);
            split2(v11.x, v11.y, ah[3], al[3]);
#pragma unroll
            for (int nt = 0; nt < 8; nt++) {
                unsigned bh[2], bl[2];
                int n = nt * 8 + g;
                bh[0] = W1p[0][8 * kt + t][n];
                bh[1] = W1p[0][8 * kt + t + 4][n];
                bl[0] = W1p[1][8 * kt + t][n];
                bl[1] = W1p[1][8 * kt + t + 4][n];
                mma_bf16(c1[nt], ah, bh);
                mma_bf16(c1[nt], al, bh);
                mma_bf16(c1[nt], ah, bl);
            }
        }

        // ---------------- transition: +b1, ssp, split -> A2 frags (regs only) ----
        unsigned a2h[4][4], a2l[4][4];
#pragma unroll
        for (int kt2 = 0; kt2 < 4; kt2++) {
            int n0 = 2 * kt2, n1 = 2 * kt2 + 1;
            float h00 = sspf(c1[n0][0] + b1r[2 * n0]);
            float h01 = sspf(c1[n0][1] + b1r[2 * n0 + 1]);
            split2(h00, h01, a2h[kt2][0], a2l[kt2][0]);
            float h10 = sspf(c1[n0][2] + b1r[2 * n0]);
            float h11 = sspf(c1[n0][3] + b1r[2 * n0 + 1]);
            split2(h10, h11, a2h[kt2][1], a2l[kt2][1]);
            float h20 = sspf(c1[n1][0] + b1r[2 * n1]);
            float h21 = sspf(c1[n1][1] + b1r[2 * n1 + 1]);
            split2(h20, h21, a2h[kt2][2], a2l[kt2][2]);
            float h30 = sspf(c1[n1][2] + b1r[2 * n1]);
            float h31 = sspf(c1[n1][3] + b1r[2 * n1 + 1]);
            split2(h30, h31, a2h[kt2][3], a2l[kt2][3]);
        }

        // epilogue row metadata
        int e_lo = mb / 36, e_hi = (mb + 15) / 36;
        int s0 = ea - e_lo, s1 = eb - e_lo;     // slot 0/1
        bool skip0 = (ja == e0g + ea);
        bool skip1 = (jb == e0g + eb);

        // ---------------- GEMM2 (in n-halves) + epilogue ----------------
#pragma unroll
        for (int half = 0; half < 2; half++) {
            float c2[8][4];
#pragma unroll
            for (int nt = 0; nt < 8; nt++)
#pragma unroll
                for (int q = 0; q < 4; q++) c2[nt][q] = 0.f;

#pragma unroll
            for (int kt2 = 0; kt2 < 4; kt2++) {
#pragma unroll
                for (int nt = 0; nt < 8; nt++) {
                    unsigned bh[2], bl[2];
                    int nn = half * 64 + nt * 8 + g;
                    bh[0] = W2p[0][8 * kt2 + t][nn];
                    bh[1] = W2p[0][8 * kt2 + t + 4][nn];
                    bl[0] = W2p[1][8 * kt2 + t][nn];
                    bl[1] = W2p[1][8 * kt2 + t + 4][nn];
                    mma_bf16(c2[nt], a2h[kt2], bh);
                    mma_bf16(c2[nt], a2l[kt2], bh);
                    mma_bf16(c2[nt], a2h[kt2], bl);
                }
            }

            // multiply by zj, accumulate per-slot
            float acc0[8][2], acc1[8][2];
#pragma unroll
            for (int nt = 0; nt < 8; nt++) {
                acc0[nt][0] = acc0[nt][1] = 0.f;
                acc1[nt][0] = acc1[nt][1] = 0.f;
            }
#pragma unroll
            for (int nt = 0; nt < 8; nt++) {
                int k0 = half * 64 + nt * 8 + 2 * t;
                float2 bb = *(const float2*)&b2g[k0];
                float2 zj0 = skip0 ? make_float2(0.f, 0.f)
                                   : *(const float2*)&zrow[ja * 128 + k0];
                float2 zj1 = skip1 ? make_float2(0.f, 0.f)
                                   : *(const float2*)&zrow[jb * 128 + k0];
                float p0 = (c2[nt][0] + bb.x) * zj0.x;
                float p1 = (c2[nt][1] + bb.y) * zj0.y;
                float p2 = (c2[nt][2] + bb.x) * zj1.x;
                float p3 = (c2[nt][3] + bb.y) * zj1.y;
                if (s0 == 0) { acc0[nt][0] += p0; acc0[nt][1] += p1; }
                else         { acc1[nt][0] += p0; acc1[nt][1] += p1; }
                if (s1 == 0) { acc0[nt][0] += p2; acc0[nt][1] += p3; }
                else         { acc1[nt][0] += p2; acc1[nt][1] += p3; }
            }

            // shfl-reduce over the 8 row-groups (lanes stride 4), atomics from lanes 0-3
#pragma unroll
            for (int nt = 0; nt < 8; nt++) {
#pragma unroll
                for (int q = 0; q < 2; q++) {
                    float v = acc0[nt][q];
                    v += __shfl_down_sync(0xffffffffu, v, 16);
                    v += __shfl_down_sync(0xffffffffu, v, 8);
                    v += __shfl_down_sync(0xffffffffu, v, 4);
                    float w = acc1[nt][q];
                    w += __shfl_down_sync(0xffffffffu, w, 16);
                    w += __shfl_down_sync(0xffffffffu, w, 8);
                    w += __shfl_down_sync(0xffffffffu, w, 4);
                    if (lane < 4) {
                        int k0 = half * 64 + nt * 8 + 2 * lane + q;
                        atomicAdd(&z_s[e_lo][k0], v);
                        if (e_hi != e_lo) atomicAdd(&z_s[e_hi][k0], w);
                    }
                }
            }
        } // half
    } // m-tile

    __syncthreads();
    for (int idx = tid; idx < 1024; idx += 288) {
        int e = idx >> 7, k = idx & 127;
        z[(((long)b * 32 + e0g + e) << 7) + k] = z_s[e][k];
    }
}

// ---------------------------------------------------------------------------
// launch
// ---------------------------------------------------------------------------
extern "C" void kernel_launch(void* const* d_in, const int* in_sizes, int n_in,
                              void* d_out, int out_size)
{
    const float* dists = (const float*)d_in[0];
    const float* emb_e = (const float*)d_in[1];
    const float* emb_n = (const float*)d_in[2];
    const float* w1    = (const float*)d_in[3];
    const float* b1    = (const float*)d_in[4];
    const float* w2    = (const float*)d_in[5];
    const float* b2    = (const float*)d_in[6];
    const float* win   = (const float*)d_in[7];
    const float* wo1   = (const float*)d_in[8];
    const float* bo1   = (const float*)d_in[9];
    const float* wo2   = (const float*)d_in[10];
    const float* bo2   = (const float*)d_in[11];
    float* out = (float*)d_out;

    float *xs, *zsv, *zv, *h2;
    cudaGetSymbolAddress((void**)&xs,  g_xs);
    cudaGetSymbolAddress((void**)&zsv, g_zs);
    cudaGetSymbolAddress((void**)&zv,  g_z);
    cudaGetSymbolAddress((void**)&h2,  g_h2);

    init_xs_kernel<<<(BATCH * NELEC * EDIM + 255) / 256, 256>>>(emb_e, xs);
    init_zsnuc_kernel<<<(BATCH * NNUC * KDIM + 255) / 256, 256>>>(emb_n, zsv);

    for (int t = 0; t < 3; t++) {
        linear_kernel<false, false, false><<<BATCH, 256>>>(
            xs, win + t * KDIM * EDIM, nullptr, nullptr, zsv, NALL * KDIM);

        pairconv_mma_kernel<<<BATCH * 4, 288>>>(
            dists, w1 + t * HIDK * BASIS, b1 + t * HIDK,
            w2 + t * KDIM * HIDK, b2 + t * KDIM, zsv, zv);

        linear_kernel<true, true, false><<<BATCH, 256>>>(
            zv, wo1 + t * HIDO * KDIM, bo1 + t * HIDO, nullptr, h2, NELEC * KDIM);

        float* dst = (t == 2) ? out : xs;
        linear_kernel<true, false, true><<<BATCH, 256>>>(
            h2, wo2 + t * EDIM * HIDO, bo2 + t * EDIM, xs, dst, NELEC * EDIM);
    }
}

// round 5
// speedup vs baseline: 1.8133x; 1.3098x over previous
#include <cuda_runtime.h>
#include <cstdint>

#define BATCH  512
#define NELEC  32
#define NALL   36
#define NNUC   4
#define BASIS  32
#define KDIM   128
#define EDIM   128
#define HIDK   64
#define HIDO   128

// Scratch (device globals)
__device__ float g_xs[BATCH * NELEC * EDIM];
__device__ float g_zs[BATCH * NALL * KDIM];
__device__ float g_z [BATCH * NELEC * KDIM];
__device__ float g_h2[BATCH * NELEC * HIDO];

// Packed fp32x2 FMA (for the fp32 linear layers)
#define FMA_F32X2(d, a, b, c) \
    asm("fma.rn.f32x2 %0, %1, %2, %3;" : "=l"(d) : "l"(a), "l"(b), "l"(c))

__device__ __forceinline__ float f2lo(unsigned long long v) { return __uint_as_float((unsigned)v); }
__device__ __forceinline__ float f2hi(unsigned long long v) { return __uint_as_float((unsigned)(v >> 32)); }

__device__ __forceinline__ float sspf(float x) {
    float e = __expf(-fabsf(x));
    float l = __logf(1.0f + e);
    return fmaxf(x, 0.0f) + l - 0.69314718055994530942f;
}

// ---------------- bf16 MMA helpers ----------------
__device__ __forceinline__ void mma_bf16(float* c, const unsigned* a, const unsigned* b) {
    asm volatile("mma.sync.aligned.m16n8k16.row.col.f32.bf16.bf16.f32 "
        "{%0,%1,%2,%3}, {%4,%5,%6,%7}, {%8,%9}, {%0,%1,%2,%3};"
        : "+f"(c[0]), "+f"(c[1]), "+f"(c[2]), "+f"(c[3])
        : "r"(a[0]), "r"(a[1]), "r"(a[2]), "r"(a[3]), "r"(b[0]), "r"(b[1]));
}
// bf16x3: c += (Ah+Al)*(Bh+Bl) approx (drop Al*Bl)
__device__ __forceinline__ void mma3(float* c, const unsigned* ah, const unsigned* al,
                                     const unsigned* bh, const unsigned* bl) {
    mma_bf16(c, ah, bh);
    mma_bf16(c, al, bh);
    mma_bf16(c, ah, bl);
}

__device__ __forceinline__ unsigned pack_bf16(float f0, float f1) {
    unsigned r;
    asm("cvt.rn.bf16x2.f32 %0, %1, %2;" : "=r"(r) : "f"(f1), "f"(f0));
    return r;
}
__device__ __forceinline__ void split2(float f0, float f1, unsigned &hi, unsigned &lo) {
    hi = pack_bf16(f0, f1);
    float h0 = __uint_as_float(hi << 16);
    float h1 = __uint_as_float(hi & 0xFFFF0000u);
    lo = pack_bf16(f0 - h0, f1 - h1);
}

__device__ __forceinline__ void ldm_x4(unsigned* r, const void* p) {
    unsigned a = (unsigned)__cvta_generic_to_shared(p);
    asm volatile("ldmatrix.sync.aligned.m8n8.x4.shared.b16 {%0,%1,%2,%3}, [%4];"
                 : "=r"(r[0]), "=r"(r[1]), "=r"(r[2]), "=r"(r[3]) : "r"(a));
}

// ---------------------------------------------------------------------------
// init / clear kernels
// ---------------------------------------------------------------------------
__global__ void init_xs_kernel(const float* __restrict__ emb_e, float* __restrict__ xs) {
    int idx = blockIdx.x * blockDim.x + threadIdx.x;
    if (idx < BATCH * NELEC * EDIM) xs[idx] = emb_e[idx & (NELEC * EDIM - 1)];
}

__global__ void init_zsnuc_kernel(const float* __restrict__ emb_n, float* __restrict__ zs) {
    int idx = blockIdx.x * blockDim.x + threadIdx.x;
    if (idx < BATCH * NNUC * KDIM) {
        int d = idx & 127;
        int m = (idx >> 7) & 3;
        int b = idx >> 9;
        zs[(b * NALL + NELEC + m) * KDIM + d] = emb_n[m * KDIM + d];
    }
}

__global__ void clear_z_kernel(float* __restrict__ z) {
    int idx = blockIdx.x * blockDim.x + threadIdx.x;
    ((float4*)z)[idx] = make_float4(0.f, 0.f, 0.f, 0.f);
}

// ---------------------------------------------------------------------------
// fp32 FFMA2 linear (unchanged — passing)
// ---------------------------------------------------------------------------
template <bool USE_BIAS, bool ACT, bool RES>
__global__ __launch_bounds__(256) void linear_kernel(
    const float* __restrict__ in, const float* __restrict__ W,
    const float* __restrict__ bias, const float* __restrict__ res,
    float* __restrict__ out, int out_bstride)
{
    __shared__ __align__(16) float in_s[32][128];
    __shared__ __align__(16) float Ws_s[128][132];

    int b = blockIdx.x;
    int tid = threadIdx.x;
    const float* inb = in + b * 4096;

#pragma unroll
    for (int q = 0; q < 4; q++) {
        int i4 = tid + q * 256;
        ((float4*)in_s)[i4] = ((const float4*)inb)[i4];
    }
#pragma unroll
    for (int q = 0; q < 16; q++) {
        int idx4 = tid + q * 256;
        int n = idx4 >> 5, d4 = idx4 & 31;
        *(float4*)&Ws_s[n][d4 * 4] = *(const float4*)&W[n * 128 + d4 * 4];
    }
    __syncthreads();

    int tx = tid & 31, ty = tid >> 5;
    int e0 = ty * 4;

    unsigned long long acc[4][4];
#pragma unroll
    for (int i = 0; i < 4; i++)
#pragma unroll
        for (int m = 0; m < 4; m++) acc[i][m] = 0ull;

#pragma unroll 8
    for (int q = 0; q < 32; q++) {
        ulonglong2 a2[4], wr[4];
#pragma unroll
        for (int i = 0; i < 4; i++)
            a2[i] = *(const ulonglong2*)&in_s[e0 + i][q * 4];
#pragma unroll
        for (int m = 0; m < 4; m++)
            wr[m] = *(const ulonglong2*)&Ws_s[tx + 32 * m][q * 4];
#pragma unroll
        for (int i = 0; i < 4; i++) {
#pragma unroll
            for (int m = 0; m < 4; m++) {
                FMA_F32X2(acc[i][m], wr[m].x, a2[i].x, acc[i][m]);
                FMA_F32X2(acc[i][m], wr[m].y, a2[i].y, acc[i][m]);
            }
        }
    }

    float bi[4] = {0.f, 0.f, 0.f, 0.f};
    if (USE_BIAS) {
#pragma unroll
        for (int m = 0; m < 4; m++) bi[m] = bias[tx + 32 * m];
    }
#pragma unroll
    for (int i = 0; i < 4; i++) {
#pragma unroll
        for (int m = 0; m < 4; m++) {
            int n = tx + 32 * m;
            float v = f2lo(acc[i][m]) + f2hi(acc[i][m]) + bi[m];
            if (ACT) v = sspf(v);
            if (RES) v += res[b * 4096 + (e0 + i) * 128 + n];
            out[b * out_bstride + (e0 + i) * 128 + n] = v;
        }
    }
}

// ---------------------------------------------------------------------------
// Pair conv, mma.sync bf16x3 + ldmatrix B-frags + deferred epilogue.
// CTA = (b, 8 electrons): 288 rows = 9 warps x 2 m16-tiles.
// Weights in smem as bf16 [n][k] rows (hi/lo planes), pads chosen so the
// 8 ldmatrix row addresses hit disjoint bank groups (strides 20/36 words).
// z accumulated via global atomicAdd (g_z cleared beforehand).
// ---------------------------------------------------------------------------
__global__ __launch_bounds__(288, 2) void pairconv_mma_kernel(
    const float* __restrict__ dists,   // (B,32,36,32)
    const float* __restrict__ w1,      // (64,32)
    const float* __restrict__ b1g,     // (64)
    const float* __restrict__ w2,      // (128,64)
    const float* __restrict__ b2g,     // (128)
    const float* __restrict__ zs,      // (B,36,128)
    float* __restrict__ z)             // (B,32,128), pre-zeroed
{
    __shared__ unsigned short W1s[2][64][40];    // [plane][n][k] bf16, pad 40
    __shared__ unsigned short W2s[2][128][72];   // [plane][n][k] bf16, pad 72

    int tid = threadIdx.x;
    int b = blockIdx.x >> 2;
    int e0g = (blockIdx.x & 3) * 8;
    int wid = tid >> 5, lane = tid & 31;
    int g = lane >> 2, t = lane & 3;
    int lr = lane & 7, lm = lane >> 3;   // ldmatrix row / matrix-select

    // pre-split weights into smem planes (packed bf16x2 word per k-pair)
    for (int idx = tid; idx < 64 * 16; idx += 288) {
        int n = idx >> 4, kp = idx & 15;
        unsigned hi, lo;
        split2(w1[n * 32 + 2 * kp], w1[n * 32 + 2 * kp + 1], hi, lo);
        *(unsigned*)&W1s[0][n][2 * kp] = hi;
        *(unsigned*)&W1s[1][n][2 * kp] = lo;
    }
    for (int idx = tid; idx < 128 * 32; idx += 288) {
        int n = idx >> 5, kp = idx & 31;
        unsigned hi, lo;
        split2(w2[n * 64 + 2 * kp], w2[n * 64 + 2 * kp + 1], hi, lo);
        *(unsigned*)&W2s[0][n][2 * kp] = hi;
        *(unsigned*)&W2s[1][n][2 * kp] = lo;
    }
    __syncthreads();

    const float* drow = dists + ((long)(b * 32 + e0g) * 36) * 32;
    const float* zrow = zs + b * (36 * 128);

    int e_lo = (wid * 32) / 36;          // warp's electron slots (local 0..7)
    int e_hi = (wid * 32 + 31) / 36;

#pragma unroll
    for (int half = 0; half < 2; half++) {
        float acc0[8][2], acc1[8][2];
#pragma unroll
        for (int nt = 0; nt < 8; nt++) {
            acc0[nt][0] = acc0[nt][1] = 0.f;
            acc1[nt][0] = acc1[nt][1] = 0.f;
        }

#pragma unroll
        for (int i = 0; i < 2; i++) {
            int mb = wid * 32 + i * 16;
            int r0 = mb + g, r1 = r0 + 8;
            int ea = r0 / 36, ja = r0 - 36 * ea;
            int eb = r1 / 36, jb = r1 - 36 * eb;
            bool skip0 = (ja == e0g + ea);
            bool skip1 = (jb == e0g + eb);
            int s0 = ea - e_lo, s1 = eb - e_lo;

            // ---- GEMM1: C1[16,64] = db x W1^T (recomputed per half) ----
            unsigned ah[2][4], al[2][4];
#pragma unroll
            for (int kt = 0; kt < 2; kt++) {
                int col = 16 * kt + 2 * t;
                float2 v00 = *(const float2*)&drow[(ea * 36 + ja) * 32 + col];
                float2 v10 = *(const float2*)&drow[(eb * 36 + jb) * 32 + col];
                float2 v01 = *(const float2*)&drow[(ea * 36 + ja) * 32 + col + 8];
                float2 v11 = *(const float2*)&drow[(eb * 36 + jb) * 32 + col + 8];
                split2(v00.x, v00.y, ah[kt][0], al[kt][0]);
                split2(v10.x, v10.y, ah[kt][1], al[kt][1]);
                split2(v01.x, v01.y, ah[kt][2], al[kt][2]);
                split2(v11.x, v11.y, ah[kt][3], al[kt][3]);
            }
            float c1[8][4];
#pragma unroll
            for (int nt = 0; nt < 8; nt++) {
#pragma unroll
                for (int q = 0; q < 4; q++) c1[nt][q] = 0.f;
                unsigned bh[4], bl[4];
                ldm_x4(bh, &W1s[0][nt * 8 + lr][8 * lm]);
                ldm_x4(bl, &W1s[1][nt * 8 + lr][8 * lm]);
                mma3(c1[nt], ah[0], al[0], &bh[0], &bl[0]);
                mma3(c1[nt], ah[1], al[1], &bh[2], &bl[2]);
            }

            // ---- transition: +b1, ssp, split -> A2 frags ----
            unsigned a2h[4][4], a2l[4][4];
#pragma unroll
            for (int kt2 = 0; kt2 < 4; kt2++) {
                int n0 = 2 * kt2, n1 = n0 + 1;
                float2 bb0 = *(const float2*)&b1g[n0 * 8 + 2 * t];
                float2 bb1 = *(const float2*)&b1g[n1 * 8 + 2 * t];
                split2(sspf(c1[n0][0] + bb0.x), sspf(c1[n0][1] + bb0.y), a2h[kt2][0], a2l[kt2][0]);
                split2(sspf(c1[n0][2] + bb0.x), sspf(c1[n0][3] + bb0.y), a2h[kt2][1], a2l[kt2][1]);
                split2(sspf(c1[n1][0] + bb1.x), sspf(c1[n1][1] + bb1.y), a2h[kt2][2], a2l[kt2][2]);
                split2(sspf(c1[n1][2] + bb1.x), sspf(c1[n1][3] + bb1.y), a2h[kt2][3], a2l[kt2][3]);
            }

            // ---- GEMM2 (this n-half) fused with product epilogue ----
#pragma unroll
            for (int nt = 0; nt < 8; nt++) {
                int nn = half * 64 + nt * 8;
                unsigned h0[4], h1[4], l0[4], l1[4];
                ldm_x4(h0, &W2s[0][nn + lr][8 * lm]);
                ldm_x4(h1, &W2s[0][nn + lr][32 + 8 * lm]);
                ldm_x4(l0, &W2s[1][nn + lr][8 * lm]);
                ldm_x4(l1, &W2s[1][nn + lr][32 + 8 * lm]);
                float c2[4] = {0.f, 0.f, 0.f, 0.f};
                mma3(c2, a2h[0], a2l[0], &h0[0], &l0[0]);
                mma3(c2, a2h[1], a2l[1], &h0[2], &l0[2]);
                mma3(c2, a2h[2], a2l[2], &h1[0], &l1[0]);
                mma3(c2, a2h[3], a2l[3], &h1[2], &l1[2]);

                int k0 = nn + 2 * t;
                float2 bb = *(const float2*)&b2g[k0];
                float2 zj0 = skip0 ? make_float2(0.f, 0.f)
                                   : *(const float2*)&zrow[ja * 128 + k0];
                float2 zj1 = skip1 ? make_float2(0.f, 0.f)
                                   : *(const float2*)&zrow[jb * 128 + k0];
                float p0 = (c2[0] + bb.x) * zj0.x;
                float p1 = (c2[1] + bb.y) * zj0.y;
                float p2 = (c2[2] + bb.x) * zj1.x;
                float p3 = (c2[3] + bb.y) * zj1.y;
                if (s0 == 0) { acc0[nt][0] += p0; acc0[nt][1] += p1; }
                else         { acc1[nt][0] += p0; acc1[nt][1] += p1; }
                if (s1 == 0) { acc0[nt][0] += p2; acc0[nt][1] += p3; }
                else         { acc1[nt][0] += p2; acc1[nt][1] += p3; }
            }
        } // m-tile

        // ---- deferred shfl-reduce (once per half) + global REDG ----
#pragma unroll
        for (int nt = 0; nt < 8; nt++) {
#pragma unroll
            for (int q = 0; q < 2; q++) {
                float v = acc0[nt][q];
                v += __shfl_down_sync(0xffffffffu, v, 16);
                v += __shfl_down_sync(0xffffffffu, v, 8);
                v += __shfl_down_sync(0xffffffffu, v, 4);
                float w = acc1[nt][q];
                w += __shfl_down_sync(0xffffffffu, w, 16);
                w += __shfl_down_sync(0xffffffffu, w, 8);
                w += __shfl_down_sync(0xffffffffu, w, 4);
                if (lane < 4) {
                    int k = half * 64 + nt * 8 + 2 * lane + q;
                    atomicAdd(&z[((long)(b * 32 + e0g + e_lo) << 7) + k], v);
                    if (e_hi != e_lo)
                        atomicAdd(&z[((long)(b * 32 + e0g + e_hi) << 7) + k], w);
                }
            }
        }
    } // half
}

// ---------------------------------------------------------------------------
// launch
// ---------------------------------------------------------------------------
extern "C" void kernel_launch(void* const* d_in, const int* in_sizes, int n_in,
                              void* d_out, int out_size)
{
    const float* dists = (const float*)d_in[0];
    const float* emb_e = (const float*)d_in[1];
    const float* emb_n = (const float*)d_in[2];
    const float* w1    = (const float*)d_in[3];
    const float* b1    = (const float*)d_in[4];
    const float* w2    = (const float*)d_in[5];
    const float* b2    = (const float*)d_in[6];
    const float* win   = (const float*)d_in[7];
    const float* wo1   = (const float*)d_in[8];
    const float* bo1   = (const float*)d_in[9];
    const float* wo2   = (const float*)d_in[10];
    const float* bo2   = (const float*)d_in[11];
    float* out = (float*)d_out;

    float *xs, *zsv, *zv, *h2;
    cudaGetSymbolAddress((void**)&xs,  g_xs);
    cudaGetSymbolAddress((void**)&zsv, g_zs);
    cudaGetSymbolAddress((void**)&zv,  g_z);
    cudaGetSymbolAddress((void**)&h2,  g_h2);

    init_xs_kernel<<<(BATCH * NELEC * EDIM + 255) / 256, 256>>>(emb_e, xs);
    init_zsnuc_kernel<<<(BATCH * NNUC * KDIM + 255) / 256, 256>>>(emb_n, zsv);

    for (int t = 0; t < 3; t++) {
        linear_kernel<false, false, false><<<BATCH, 256>>>(
            xs, win + t * KDIM * EDIM, nullptr, nullptr, zsv, NALL * KDIM);

        clear_z_kernel<<<(BATCH * NELEC * KDIM / 4) / 256, 256>>>(zv);

        pairconv_mma_kernel<<<BATCH * 4, 288>>>(
            dists, w1 + t * HIDK * BASIS, b1 + t * HIDK,
            w2 + t * KDIM * HIDK, b2 + t * KDIM, zsv, zv);

        linear_kernel<true, true, false><<<BATCH, 256>>>(
            zv, wo1 + t * HIDO * KDIM, bo1 + t * HIDO, nullptr, h2, NELEC * KDIM);

        float* dst = (t == 2) ? out : xs;
        linear_kernel<true, false, true><<<BATCH, 256>>>(
            h2, wo2 + t * EDIM * HIDO, bo2 + t * EDIM, xs, dst, NELEC * EDIM);
    }
}

// round 6
// speedup vs baseline: 1.9483x; 1.0744x over previous
#include <cuda_runtime.h>
#include <cstdint>

#define BATCH  512
#define NELEC  32
#define NALL   36
#define NNUC   4
#define BASIS  32
#define KDIM   128
#define EDIM   128
#define HIDK   64
#define HIDO   128

// Scratch (device globals)
__device__ float g_xs[BATCH * NELEC * EDIM];
__device__ float g_zs[BATCH * NALL * KDIM];
__device__ float g_z [BATCH * NELEC * KDIM];
__device__ float g_h2[BATCH * NELEC * HIDO];

// Packed fp32x2 FMA (for the fp32 linear layers)
#define FMA_F32X2(d, a, b, c) \
    asm("fma.rn.f32x2 %0, %1, %2, %3;" : "=l"(d) : "l"(a), "l"(b), "l"(c))

__device__ __forceinline__ float f2lo(unsigned long long v) { return __uint_as_float((unsigned)v); }
__device__ __forceinline__ float f2hi(unsigned long long v) { return __uint_as_float((unsigned)(v >> 32)); }

__device__ __forceinline__ float sspf(float x) {
    float e = __expf(-fabsf(x));
    float l = __logf(1.0f + e);
    return fmaxf(x, 0.0f) + l - 0.69314718055994530942f;
}

// ---------------- bf16 MMA helpers ----------------
__device__ __forceinline__ void mma_bf16(float* c, const unsigned* a, const unsigned* b) {
    asm volatile("mma.sync.aligned.m16n8k16.row.col.f32.bf16.bf16.f32 "
        "{%0,%1,%2,%3}, {%4,%5,%6,%7}, {%8,%9}, {%0,%1,%2,%3};"
        : "+f"(c[0]), "+f"(c[1]), "+f"(c[2]), "+f"(c[3])
        : "r"(a[0]), "r"(a[1]), "r"(a[2]), "r"(a[3]), "r"(b[0]), "r"(b[1]));
}
// bf16x3: c += (Ah+Al)*(Bh+Bl) approx (drop Al*Bl)
__device__ __forceinline__ void mma3(float* c, const unsigned* ah, const unsigned* al,
                                     const unsigned* bh, const unsigned* bl) {
    mma_bf16(c, ah, bh);
    mma_bf16(c, al, bh);
    mma_bf16(c, ah, bl);
}

__device__ __forceinline__ unsigned pack_bf16(float f0, float f1) {
    unsigned r;
    asm("cvt.rn.bf16x2.f32 %0, %1, %2;" : "=r"(r) : "f"(f1), "f"(f0));
    return r;
}
__device__ __forceinline__ void split2(float f0, float f1, unsigned &hi, unsigned &lo) {
    hi = pack_bf16(f0, f1);
    float h0 = __uint_as_float(hi << 16);
    float h1 = __uint_as_float(hi & 0xFFFF0000u);
    lo = pack_bf16(f0 - h0, f1 - h1);
}

__device__ __forceinline__ void ldm_x4(unsigned* r, const void* p) {
    unsigned a = (unsigned)__cvta_generic_to_shared(p);
    asm volatile("ldmatrix.sync.aligned.m8n8.x4.shared.b16 {%0,%1,%2,%3}, [%4];"
                 : "=r"(r[0]), "=r"(r[1]), "=r"(r[2]), "=r"(r[3]) : "r"(a));
}

// ---------------------------------------------------------------------------
// init kernels
// ---------------------------------------------------------------------------
__global__ void init_xs_kernel(const float* __restrict__ emb_e, float* __restrict__ xs) {
    int idx = blockIdx.x * blockDim.x + threadIdx.x;
    if (idx < BATCH * NELEC * EDIM) xs[idx] = emb_e[idx & (NELEC * EDIM - 1)];
}

__global__ void init_zsnuc_kernel(const float* __restrict__ emb_n, float* __restrict__ zs) {
    int idx = blockIdx.x * blockDim.x + threadIdx.x;
    if (idx < BATCH * NNUC * KDIM) {
        int d = idx & 127;
        int m = (idx >> 7) & 3;
        int b = idx >> 9;
        zs[(b * NALL + NELEC + m) * KDIM + d] = emb_n[m * KDIM + d];
    }
}

// ---------------------------------------------------------------------------
// fp32 FFMA2 linear (unchanged — passing)
// ---------------------------------------------------------------------------
template <bool USE_BIAS, bool ACT, bool RES>
__global__ __launch_bounds__(256) void linear_kernel(
    const float* __restrict__ in, const float* __restrict__ W,
    const float* __restrict__ bias, const float* __restrict__ res,
    float* __restrict__ out, int out_bstride)
{
    __shared__ __align__(16) float in_s[32][128];
    __shared__ __align__(16) float Ws_s[128][132];

    int b = blockIdx.x;
    int tid = threadIdx.x;
    const float* inb = in + b * 4096;

#pragma unroll
    for (int q = 0; q < 4; q++) {
        int i4 = tid + q * 256;
        ((float4*)in_s)[i4] = ((const float4*)inb)[i4];
    }
#pragma unroll
    for (int q = 0; q < 16; q++) {
        int idx4 = tid + q * 256;
        int n = idx4 >> 5, d4 = idx4 & 31;
        *(float4*)&Ws_s[n][d4 * 4] = *(const float4*)&W[n * 128 + d4 * 4];
    }
    __syncthreads();

    int tx = tid & 31, ty = tid >> 5;
    int e0 = ty * 4;

    unsigned long long acc[4][4];
#pragma unroll
    for (int i = 0; i < 4; i++)
#pragma unroll
        for (int m = 0; m < 4; m++) acc[i][m] = 0ull;

#pragma unroll 8
    for (int q = 0; q < 32; q++) {
        ulonglong2 a2[4], wr[4];
#pragma unroll
        for (int i = 0; i < 4; i++)
            a2[i] = *(const ulonglong2*)&in_s[e0 + i][q * 4];
#pragma unroll
        for (int m = 0; m < 4; m++)
            wr[m] = *(const ulonglong2*)&Ws_s[tx + 32 * m][q * 4];
#pragma unroll
        for (int i = 0; i < 4; i++) {
#pragma unroll
            for (int m = 0; m < 4; m++) {
                FMA_F32X2(acc[i][m], wr[m].x, a2[i].x, acc[i][m]);
                FMA_F32X2(acc[i][m], wr[m].y, a2[i].y, acc[i][m]);
            }
        }
    }

    float bi[4] = {0.f, 0.f, 0.f, 0.f};
    if (USE_BIAS) {
#pragma unroll
        for (int m = 0; m < 4; m++) bi[m] = bias[tx + 32 * m];
    }
#pragma unroll
    for (int i = 0; i < 4; i++) {
#pragma unroll
        for (int m = 0; m < 4; m++) {
            int n = tx + 32 * m;
            float v = f2lo(acc[i][m]) + f2hi(acc[i][m]) + bi[m];
            if (ACT) v = sspf(v);
            if (RES) v += res[b * 4096 + (e0 + i) * 128 + n];
            out[b * out_bstride + (e0 + i) * 128 + n] = v;
        }
    }
}

// ---------------------------------------------------------------------------
// Pair conv, mma.sync bf16x3 + ldmatrix.
// m-tile OUTER: GEMM1 + ssp transition once per m-tile; GEMM2 per n-half with
// immediate shfl-reduced epilogue into smem z_s (atomicAdd, no global atomics).
// Accumulator chains split (c1: 3+3, c2: 6+6) to halve RAW stall depth.
// ---------------------------------------------------------------------------
__global__ __launch_bounds__(288, 2) void pairconv_mma_kernel(
    const float* __restrict__ dists,   // (B,32,36,32)
    const float* __restrict__ w1,      // (64,32)
    const float* __restrict__ b1g,     // (64)
    const float* __restrict__ w2,      // (128,64)
    const float* __restrict__ b2g,     // (128)
    const float* __restrict__ zs,      // (B,36,128)
    float* __restrict__ z)             // (B,32,128)
{
    __shared__ unsigned short W1s[2][64][40];    // [plane][n][k] bf16, pad 40
    __shared__ unsigned short W2s[2][128][72];   // [plane][n][k] bf16, pad 72
    __shared__ float z_s[8][128];

    int tid = threadIdx.x;
    int b = blockIdx.x >> 2;
    int e0g = (blockIdx.x & 3) * 8;
    int wid = tid >> 5, lane = tid & 31;
    int g = lane >> 2, t = lane & 3;
    int lr = lane & 7, lm = lane >> 3;   // ldmatrix row / matrix-select

    // pre-split weights into smem planes
    for (int idx = tid; idx < 64 * 16; idx += 288) {
        int n = idx >> 4, kp = idx & 15;
        unsigned hi, lo;
        split2(w1[n * 32 + 2 * kp], w1[n * 32 + 2 * kp + 1], hi, lo);
        *(unsigned*)&W1s[0][n][2 * kp] = hi;
        *(unsigned*)&W1s[1][n][2 * kp] = lo;
    }
    for (int idx = tid; idx < 128 * 32; idx += 288) {
        int n = idx >> 5, kp = idx & 31;
        unsigned hi, lo;
        split2(w2[n * 64 + 2 * kp], w2[n * 64 + 2 * kp + 1], hi, lo);
        *(unsigned*)&W2s[0][n][2 * kp] = hi;
        *(unsigned*)&W2s[1][n][2 * kp] = lo;
    }
    for (int idx = tid; idx < 1024; idx += 288) ((float*)z_s)[idx] = 0.f;
    __syncthreads();

    const float* drow = dists + ((long)(b * 32 + e0g) * 36) * 32;
    const float* zrow = zs + b * (36 * 128);

    int e_lo = (wid * 32) / 36;          // warp's electron slots (local 0..7)
    int e_hi = (wid * 32 + 31) / 36;

#pragma unroll
    for (int i = 0; i < 2; i++) {
        int mb = wid * 32 + i * 16;
        int r0 = mb + g, r1 = r0 + 8;
        int ea = r0 / 36, ja = r0 - 36 * ea;
        int eb = r1 / 36, jb = r1 - 36 * eb;
        bool skip0 = (ja == e0g + ea);
        bool skip1 = (jb == e0g + eb);
        int s0 = ea - e_lo, s1 = eb - e_lo;

        // ---- A-fragments of db (once per m-tile) ----
        unsigned ah[2][4], al[2][4];
#pragma unroll
        for (int kt = 0; kt < 2; kt++) {
            int col = 16 * kt + 2 * t;
            float2 v00 = *(const float2*)&drow[(ea * 36 + ja) * 32 + col];
            float2 v10 = *(const float2*)&drow[(eb * 36 + jb) * 32 + col];
            float2 v01 = *(const float2*)&drow[(ea * 36 + ja) * 32 + col + 8];
            float2 v11 = *(const float2*)&drow[(eb * 36 + jb) * 32 + col + 8];
            split2(v00.x, v00.y, ah[kt][0], al[kt][0]);
            split2(v10.x, v10.y, ah[kt][1], al[kt][1]);
            split2(v01.x, v01.y, ah[kt][2], al[kt][2]);
            split2(v11.x, v11.y, ah[kt][3], al[kt][3]);
        }

        // ---- GEMM1: C1[16,64] = db x W1^T (split accumulator chains) ----
        float c1[8][4];
#pragma unroll
        for (int nt = 0; nt < 8; nt++) {
            unsigned bh[4], bl[4];
            ldm_x4(bh, &W1s[0][nt * 8 + lr][8 * lm]);
            ldm_x4(bl, &W1s[1][nt * 8 + lr][8 * lm]);
            float cA[4] = {0.f, 0.f, 0.f, 0.f};
            float cB[4] = {0.f, 0.f, 0.f, 0.f};
            mma3(cA, ah[0], al[0], &bh[0], &bl[0]);
            mma3(cB, ah[1], al[1], &bh[2], &bl[2]);
#pragma unroll
            for (int q = 0; q < 4; q++) c1[nt][q] = cA[q] + cB[q];
        }

        // ---- transition: +b1, ssp, split -> A2 frags (once per m-tile) ----
        unsigned a2h[4][4], a2l[4][4];
#pragma unroll
        for (int kt2 = 0; kt2 < 4; kt2++) {
            int n0 = 2 * kt2, n1 = n0 + 1;
            float2 bb0 = *(const float2*)&b1g[n0 * 8 + 2 * t];
            float2 bb1 = *(const float2*)&b1g[n1 * 8 + 2 * t];
            split2(sspf(c1[n0][0] + bb0.x), sspf(c1[n0][1] + bb0.y), a2h[kt2][0], a2l[kt2][0]);
            split2(sspf(c1[n0][2] + bb0.x), sspf(c1[n0][3] + bb0.y), a2h[kt2][1], a2l[kt2][1]);
            split2(sspf(c1[n1][0] + bb1.x), sspf(c1[n1][1] + bb1.y), a2h[kt2][2], a2l[kt2][2]);
            split2(sspf(c1[n1][2] + bb1.x), sspf(c1[n1][3] + bb1.y), a2h[kt2][3], a2l[kt2][3]);
        }

        // ---- GEMM2 per n-half + epilogue ----
#pragma unroll
        for (int half = 0; half < 2; half++) {
            float acc0[8][2], acc1[8][2];
#pragma unroll
            for (int nt = 0; nt < 8; nt++) {
                int nn = half * 64 + nt * 8;
                int k0 = nn + 2 * t;

                // prefetch epilogue operands
                float2 bb = *(const float2*)&b2g[k0];
                float2 zj0 = skip0 ? make_float2(0.f, 0.f)
                                   : *(const float2*)&zrow[ja * 128 + k0];
                float2 zj1 = skip1 ? make_float2(0.f, 0.f)
                                   : *(const float2*)&zrow[jb * 128 + k0];

                unsigned h0[4], h1[4], l0[4], l1[4];
                ldm_x4(h0, &W2s[0][nn + lr][8 * lm]);
                ldm_x4(h1, &W2s[0][nn + lr][32 + 8 * lm]);
                ldm_x4(l0, &W2s[1][nn + lr][8 * lm]);
                ldm_x4(l1, &W2s[1][nn + lr][32 + 8 * lm]);

                float cA[4] = {0.f, 0.f, 0.f, 0.f};
                float cB[4] = {0.f, 0.f, 0.f, 0.f};
                mma3(cA, a2h[0], a2l[0], &h0[0], &l0[0]);
                mma3(cA, a2h[1], a2l[1], &h0[2], &l0[2]);
                mma3(cB, a2h[2], a2l[2], &h1[0], &l1[0]);
                mma3(cB, a2h[3], a2l[3], &h1[2], &l1[2]);

                float p0 = (cA[0] + cB[0] + bb.x) * zj0.x;
                float p1 = (cA[1] + cB[1] + bb.y) * zj0.y;
                float p2 = (cA[2] + cB[2] + bb.x) * zj1.x;
                float p3 = (cA[3] + cB[3] + bb.y) * zj1.y;
                acc0[nt][0] = (s0 == 0) ? p0 : 0.f;
                acc0[nt][1] = (s0 == 0) ? p1 : 0.f;
                acc1[nt][0] = (s0 == 0) ? 0.f : p0;
                acc1[nt][1] = (s0 == 0) ? 0.f : p1;
                if (s1 == 0) { acc0[nt][0] += p2; acc0[nt][1] += p3; }
                else         { acc1[nt][0] += p2; acc1[nt][1] += p3; }
            }

            // shfl-reduce over the 8 row-groups, smem atomics from lanes 0-3
#pragma unroll
            for (int nt = 0; nt < 8; nt++) {
#pragma unroll
                for (int q = 0; q < 2; q++) {
                    float v = acc0[nt][q];
                    v += __shfl_down_sync(0xffffffffu, v, 16);
                    v += __shfl_down_sync(0xffffffffu, v, 8);
                    v += __shfl_down_sync(0xffffffffu, v, 4);
                    float w = acc1[nt][q];
                    w += __shfl_down_sync(0xffffffffu, w, 16);
                    w += __shfl_down_sync(0xffffffffu, w, 8);
                    w += __shfl_down_sync(0xffffffffu, w, 4);
                    if (lane < 4) {
                        int k = half * 64 + nt * 8 + 2 * lane + q;
                        atomicAdd(&z_s[e_lo][k], v);
                        if (e_hi != e_lo) atomicAdd(&z_s[e_hi][k], w);
                    }
                }
            }
        } // half
    } // m-tile

    __syncthreads();
    for (int idx = tid; idx < 1024; idx += 288) {
        int e = idx >> 7, k = idx & 127;
        z[(((long)(b * 32 + e0g + e)) << 7) + k] = z_s[e][k];
    }
}

// ---------------------------------------------------------------------------
// launch
// ---------------------------------------------------------------------------
extern "C" void kernel_launch(void* const* d_in, const int* in_sizes, int n_in,
                              void* d_out, int out_size)
{
    const float* dists = (const float*)d_in[0];
    const float* emb_e = (const float*)d_in[1];
    const float* emb_n = (const float*)d_in[2];
    const float* w1    = (const float*)d_in[3];
    const float* b1    = (const float*)d_in[4];
    const float* w2    = (const float*)d_in[5];
    const float* b2    = (const float*)d_in[6];
    const float* win   = (const float*)d_in[7];
    const float* wo1   = (const float*)d_in[8];
    const float* bo1   = (const float*)d_in[9];
    const float* wo2   = (const float*)d_in[10];
    const float* bo2   = (const float*)d_in[11];
    float* out = (float*)d_out;

    float *xs, *zsv, *zv, *h2;
    cudaGetSymbolAddress((void**)&xs,  g_xs);
    cudaGetSymbolAddress((void**)&zsv, g_zs);
    cudaGetSymbolAddress((void**)&zv,  g_z);
    cudaGetSymbolAddress((void**)&h2,  g_h2);

    init_xs_kernel<<<(BATCH * NELEC * EDIM + 255) / 256, 256>>>(emb_e, xs);
    init_zsnuc_kernel<<<(BATCH * NNUC * KDIM + 255) / 256, 256>>>(emb_n, zsv);

    for (int t = 0; t < 3; t++) {
        linear_kernel<false, false, false><<<BATCH, 256>>>(
            xs, win + t * KDIM * EDIM, nullptr, nullptr, zsv, NALL * KDIM);

        pairconv_mma_kernel<<<BATCH * 4, 288>>>(
            dists, w1 + t * HIDK * BASIS, b1 + t * HIDK,
            w2 + t * KDIM * HIDK, b2 + t * KDIM, zsv, zv);

        linear_kernel<true, true, false><<<BATCH, 256>>>(
            zv, wo1 + t * HIDO * KDIM, bo1 + t * HIDO, nullptr, h2, NELEC * KDIM);

        float* dst = (t == 2) ? out : xs;
        linear_kernel<true, false, true><<<BATCH, 256>>>(
            h2, wo2 + t * EDIM * HIDO, bo2 + t * EDIM, xs, dst, NELEC * EDIM);
    }
}

// round 7
// speedup vs baseline: 2.0739x; 1.0645x over previous
#include <cuda_runtime.h>
#include <cstdint>

#define BATCH  512
#define NELEC  32
#define NALL   36
#define NNUC   4
#define BASIS  32
#define KDIM   128
#define EDIM   128
#define HIDK   64
#define HIDO   128

// Scratch (device globals)
__device__ float g_xs[BATCH * NELEC * EDIM];
__device__ float g_zs[BATCH * NALL * KDIM];
__device__ float g_z [BATCH * NELEC * KDIM];
__device__ float g_h2[BATCH * NELEC * HIDO];

// Packed fp32x2 FMA (for the fp32 linear layers)
#define FMA_F32X2(d, a, b, c) \
    asm("fma.rn.f32x2 %0, %1, %2, %3;" : "=l"(d) : "l"(a), "l"(b), "l"(c))

__device__ __forceinline__ float f2lo(unsigned long long v) { return __uint_as_float((unsigned)v); }
__device__ __forceinline__ float f2hi(unsigned long long v) { return __uint_as_float((unsigned)(v >> 32)); }

__device__ __forceinline__ float sspf(float x) {
    float e = __expf(-fabsf(x));
    float l = __logf(1.0f + e);
    return fmaxf(x, 0.0f) + l - 0.69314718055994530942f;
}

// ---------------- bf16 MMA helpers ----------------
__device__ __forceinline__ void mma_bf16(float* c, const unsigned* a, const unsigned* b) {
    asm volatile("mma.sync.aligned.m16n8k16.row.col.f32.bf16.bf16.f32 "
        "{%0,%1,%2,%3}, {%4,%5,%6,%7}, {%8,%9}, {%0,%1,%2,%3};"
        : "+f"(c[0]), "+f"(c[1]), "+f"(c[2]), "+f"(c[3])
        : "r"(a[0]), "r"(a[1]), "r"(a[2]), "r"(a[3]), "r"(b[0]), "r"(b[1]));
}
// bf16x3: c += (Ah+Al)*(Bh+Bl) approx (drop Al*Bl)
__device__ __forceinline__ void mma3(float* c, const unsigned* ah, const unsigned* al,
                                     const unsigned* bh, const unsigned* bl) {
    mma_bf16(c, ah, bh);
    mma_bf16(c, al, bh);
    mma_bf16(c, ah, bl);
}

__device__ __forceinline__ unsigned pack_bf16(float f0, float f1) {
    unsigned r;
    asm("cvt.rn.bf16x2.f32 %0, %1, %2;" : "=r"(r) : "f"(f1), "f"(f0));
    return r;
}
__device__ __forceinline__ void split2(float f0, float f1, unsigned &hi, unsigned &lo) {
    hi = pack_bf16(f0, f1);
    float h0 = __uint_as_float(hi << 16);
    float h1 = __uint_as_float(hi & 0xFFFF0000u);
    lo = pack_bf16(f0 - h0, f1 - h1);
}

__device__ __forceinline__ void ldm_x4(unsigned* r, const void* p) {
    unsigned a = (unsigned)__cvta_generic_to_shared(p);
    asm volatile("ldmatrix.sync.aligned.m8n8.x4.shared.b16 {%0,%1,%2,%3}, [%4];"
                 : "=r"(r[0]), "=r"(r[1]), "=r"(r[2]), "=r"(r[3]) : "r"(a));
}

// ---------------------------------------------------------------------------
// init kernels
// ---------------------------------------------------------------------------
__global__ void init_xs_kernel(const float* __restrict__ emb_e, float* __restrict__ xs) {
    int idx = blockIdx.x * blockDim.x + threadIdx.x;
    if (idx < BATCH * NELEC * EDIM) xs[idx] = emb_e[idx & (NELEC * EDIM - 1)];
}

__global__ void init_zsnuc_kernel(const float* __restrict__ emb_n, float* __restrict__ zs) {
    int idx = blockIdx.x * blockDim.x + threadIdx.x;
    if (idx < BATCH * NNUC * KDIM) {
        int d = idx & 127;
        int m = (idx >> 7) & 3;
        int b = idx >> 9;
        zs[(b * NALL + NELEC + m) * KDIM + d] = emb_n[m * KDIM + d];
    }
}

// ---------------------------------------------------------------------------
// fp32 FFMA2 linear (unchanged — passing)
// ---------------------------------------------------------------------------
template <bool USE_BIAS, bool ACT, bool RES>
__global__ __launch_bounds__(256) void linear_kernel(
    const float* __restrict__ in, const float* __restrict__ W,
    const float* __restrict__ bias, const float* __restrict__ res,
    float* __restrict__ out, int out_bstride)
{
    __shared__ __align__(16) float in_s[32][128];
    __shared__ __align__(16) float Ws_s[128][132];

    int b = blockIdx.x;
    int tid = threadIdx.x;
    const float* inb = in + b * 4096;

#pragma unroll
    for (int q = 0; q < 4; q++) {
        int i4 = tid + q * 256;
        ((float4*)in_s)[i4] = ((const float4*)inb)[i4];
    }
#pragma unroll
    for (int q = 0; q < 16; q++) {
        int idx4 = tid + q * 256;
        int n = idx4 >> 5, d4 = idx4 & 31;
        *(float4*)&Ws_s[n][d4 * 4] = *(const float4*)&W[n * 128 + d4 * 4];
    }
    __syncthreads();

    int tx = tid & 31, ty = tid >> 5;
    int e0 = ty * 4;

    unsigned long long acc[4][4];
#pragma unroll
    for (int i = 0; i < 4; i++)
#pragma unroll
        for (int m = 0; m < 4; m++) acc[i][m] = 0ull;

#pragma unroll 8
    for (int q = 0; q < 32; q++) {
        ulonglong2 a2[4], wr[4];
#pragma unroll
        for (int i = 0; i < 4; i++)
            a2[i] = *(const ulonglong2*)&in_s[e0 + i][q * 4];
#pragma unroll
        for (int m = 0; m < 4; m++)
            wr[m] = *(const ulonglong2*)&Ws_s[tx + 32 * m][q * 4];
#pragma unroll
        for (int i = 0; i < 4; i++) {
#pragma unroll
            for (int m = 0; m < 4; m++) {
                FMA_F32X2(acc[i][m], wr[m].x, a2[i].x, acc[i][m]);
                FMA_F32X2(acc[i][m], wr[m].y, a2[i].y, acc[i][m]);
            }
        }
    }

    float bi[4] = {0.f, 0.f, 0.f, 0.f};
    if (USE_BIAS) {
#pragma unroll
        for (int m = 0; m < 4; m++) bi[m] = bias[tx + 32 * m];
    }
#pragma unroll
    for (int i = 0; i < 4; i++) {
#pragma unroll
        for (int m = 0; m < 4; m++) {
            int n = tx + 32 * m;
            float v = f2lo(acc[i][m]) + f2hi(acc[i][m]) + bi[m];
            if (ACT) v = sspf(v);
            if (RES) v += res[b * 4096 + (e0 + i) * 128 + n];
            out[b * out_bstride + (e0 + i) * 128 + n] = v;
        }
    }
}

// ---------------------------------------------------------------------------
// Pair conv, mma.sync bf16x3 + ldmatrix.
// Phase 1: GEMM1 + ssp transition for BOTH m-tiles -> a2 frags (64 regs).
// Phase 2: (half, nt) outer, m-tile inner: each W2 fragment loaded ONCE and
// used for 24 MMAs; epilogue products accumulated across both m-tiles, shfl-
// reduced once per (half,nt) -> halves LDSM + SHFL + ATOMS on the binding
// L1/MIO pipe.
// ---------------------------------------------------------------------------
__global__ __launch_bounds__(288, 2) void pairconv_mma_kernel(
    const float* __restrict__ dists,   // (B,32,36,32)
    const float* __restrict__ w1,      // (64,32)
    const float* __restrict__ b1g,     // (64)
    const float* __restrict__ w2,      // (128,64)
    const float* __restrict__ b2g,     // (128)
    const float* __restrict__ zs,      // (B,36,128)
    float* __restrict__ z)             // (B,32,128)
{
    __shared__ unsigned short W1s[2][64][40];    // [plane][n][k] bf16, pad 40
    __shared__ unsigned short W2s[2][128][72];   // [plane][n][k] bf16, pad 72
    __shared__ float z_s[8][128];

    int tid = threadIdx.x;
    int b = blockIdx.x >> 2;
    int e0g = (blockIdx.x & 3) * 8;
    int wid = tid >> 5, lane = tid & 31;
    int g = lane >> 2, t = lane & 3;
    int lr = lane & 7, lm = lane >> 3;   // ldmatrix row / matrix-select

    // pre-split weights into smem planes
    for (int idx = tid; idx < 64 * 16; idx += 288) {
        int n = idx >> 4, kp = idx & 15;
        unsigned hi, lo;
        split2(w1[n * 32 + 2 * kp], w1[n * 32 + 2 * kp + 1], hi, lo);
        *(unsigned*)&W1s[0][n][2 * kp] = hi;
        *(unsigned*)&W1s[1][n][2 * kp] = lo;
    }
    for (int idx = tid; idx < 128 * 32; idx += 288) {
        int n = idx >> 5, kp = idx & 31;
        unsigned hi, lo;
        split2(w2[n * 64 + 2 * kp], w2[n * 64 + 2 * kp + 1], hi, lo);
        *(unsigned*)&W2s[0][n][2 * kp] = hi;
        *(unsigned*)&W2s[1][n][2 * kp] = lo;
    }
    for (int idx = tid; idx < 1024; idx += 288) ((float*)z_s)[idx] = 0.f;
    __syncthreads();

    const float* drow = dists + ((long)(b * 32 + e0g) * 36) * 32;
    const float* zrow = zs + b * (36 * 128);

    int e_lo = (wid * 32) / 36;          // warp's electron slots (local 0..7)
    int e_hi = (wid * 32 + 31) / 36;

    // ---- Phase 1: GEMM1 + transition for both m-tiles ----
    unsigned a2h[2][4][4], a2l[2][4][4];
    int ja_[2], jb_[2];
    bool skip0_[2], skip1_[2];
    bool hi0_[2], hi1_[2];    // row belongs to e_hi slot?

#pragma unroll
    for (int i = 0; i < 2; i++) {
        int mb = wid * 32 + i * 16;
        int r0 = mb + g, r1 = r0 + 8;
        int ea = r0 / 36, ja = r0 - 36 * ea;
        int eb = r1 / 36, jb = r1 - 36 * eb;
        ja_[i] = ja; jb_[i] = jb;
        skip0_[i] = (ja == e0g + ea);
        skip1_[i] = (jb == e0g + eb);
        hi0_[i] = (ea != e_lo);
        hi1_[i] = (eb != e_lo);

        // A-fragments of db
        unsigned ah[2][4], al[2][4];
#pragma unroll
        for (int kt = 0; kt < 2; kt++) {
            int col = 16 * kt + 2 * t;
            float2 v00 = *(const float2*)&drow[(ea * 36 + ja) * 32 + col];
            float2 v10 = *(const float2*)&drow[(eb * 36 + jb) * 32 + col];
            float2 v01 = *(const float2*)&drow[(ea * 36 + ja) * 32 + col + 8];
            float2 v11 = *(const float2*)&drow[(eb * 36 + jb) * 32 + col + 8];
            split2(v00.x, v00.y, ah[kt][0], al[kt][0]);
            split2(v10.x, v10.y, ah[kt][1], al[kt][1]);
            split2(v01.x, v01.y, ah[kt][2], al[kt][2]);
            split2(v11.x, v11.y, ah[kt][3], al[kt][3]);
        }

        // GEMM1 (split accumulator chains)
        float c1[8][4];
#pragma unroll
        for (int nt = 0; nt < 8; nt++) {
            unsigned bh[4], bl[4];
            ldm_x4(bh, &W1s[0][nt * 8 + lr][8 * lm]);
            ldm_x4(bl, &W1s[1][nt * 8 + lr][8 * lm]);
            float cA[4] = {0.f, 0.f, 0.f, 0.f};
            float cB[4] = {0.f, 0.f, 0.f, 0.f};
            mma3(cA, ah[0], al[0], &bh[0], &bl[0]);
            mma3(cB, ah[1], al[1], &bh[2], &bl[2]);
#pragma unroll
            for (int q = 0; q < 4; q++) c1[nt][q] = cA[q] + cB[q];
        }

        // transition: +b1, ssp, split -> A2 frags
#pragma unroll
        for (int kt2 = 0; kt2 < 4; kt2++) {
            int n0 = 2 * kt2, n1 = n0 + 1;
            float2 bb0 = *(const float2*)&b1g[n0 * 8 + 2 * t];
            float2 bb1 = *(const float2*)&b1g[n1 * 8 + 2 * t];
            split2(sspf(c1[n0][0] + bb0.x), sspf(c1[n0][1] + bb0.y), a2h[i][kt2][0], a2l[i][kt2][0]);
            split2(sspf(c1[n0][2] + bb0.x), sspf(c1[n0][3] + bb0.y), a2h[i][kt2][1], a2l[i][kt2][1]);
            split2(sspf(c1[n1][0] + bb1.x), sspf(c1[n1][1] + bb1.y), a2h[i][kt2][2], a2l[i][kt2][2]);
            split2(sspf(c1[n1][2] + bb1.x), sspf(c1[n1][3] + bb1.y), a2h[i][kt2][3], a2l[i][kt2][3]);
        }
    }

    // ---- Phase 2: GEMM2 with single-load W2 frags + fused epilogue ----
#pragma unroll
    for (int half = 0; half < 2; half++) {
#pragma unroll
        for (int nt = 0; nt < 8; nt++) {
            int nn = half * 64 + nt * 8;
            int k0 = nn + 2 * t;

            unsigned h0[4], h1[4], l0[4], l1[4];
            ldm_x4(h0, &W2s[0][nn + lr][8 * lm]);
            ldm_x4(h1, &W2s[0][nn + lr][32 + 8 * lm]);
            ldm_x4(l0, &W2s[1][nn + lr][8 * lm]);
            ldm_x4(l1, &W2s[1][nn + lr][32 + 8 * lm]);
            float2 bb = *(const float2*)&b2g[k0];

            float acc0[2] = {0.f, 0.f};
            float acc1[2] = {0.f, 0.f};

#pragma unroll
            for (int i = 0; i < 2; i++) {
                float2 zj0 = skip0_[i] ? make_float2(0.f, 0.f)
                                       : *(const float2*)&zrow[ja_[i] * 128 + k0];
                float2 zj1 = skip1_[i] ? make_float2(0.f, 0.f)
                                       : *(const float2*)&zrow[jb_[i] * 128 + k0];

                float cA[4] = {0.f, 0.f, 0.f, 0.f};
                float cB[4] = {0.f, 0.f, 0.f, 0.f};
                mma3(cA, a2h[i][0], a2l[i][0], &h0[0], &l0[0]);
                mma3(cA, a2h[i][1], a2l[i][1], &h0[2], &l0[2]);
                mma3(cB, a2h[i][2], a2l[i][2], &h1[0], &l1[0]);
                mma3(cB, a2h[i][3], a2l[i][3], &h1[2], &l1[2]);

                float p0 = (cA[0] + cB[0] + bb.x) * zj0.x;
                float p1 = (cA[1] + cB[1] + bb.y) * zj0.y;
                float p2 = (cA[2] + cB[2] + bb.x) * zj1.x;
                float p3 = (cA[3] + cB[3] + bb.y) * zj1.y;
                if (hi0_[i]) { acc1[0] += p0; acc1[1] += p1; }
                else         { acc0[0] += p0; acc0[1] += p1; }
                if (hi1_[i]) { acc1[0] += p2; acc1[1] += p3; }
                else         { acc0[0] += p2; acc0[1] += p3; }
            }

            // single shfl-reduce per (half,nt) over the 8 row-groups
#pragma unroll
            for (int q = 0; q < 2; q++) {
                float v = acc0[q];
                v += __shfl_down_sync(0xffffffffu, v, 16);
                v += __shfl_down_sync(0xffffffffu, v, 8);
                v += __shfl_down_sync(0xffffffffu, v, 4);
                float w = acc1[q];
                w += __shfl_down_sync(0xffffffffu, w, 16);
                w += __shfl_down_sync(0xffffffffu, w, 8);
                w += __shfl_down_sync(0xffffffffu, w, 4);
                if (lane < 4) {
                    int k = nn + 2 * lane + q;
                    atomicAdd(&z_s[e_lo][k], v);
                    if (e_hi != e_lo) atomicAdd(&z_s[e_hi][k], w);
                }
            }
        } // nt
    } // half

    __syncthreads();
    for (int idx = tid; idx < 1024; idx += 288) {
        int e = idx >> 7, k = idx & 127;
        z[(((long)(b * 32 + e0g + e)) << 7) + k] = z_s[e][k];
    }
}

// ---------------------------------------------------------------------------
// launch
// ---------------------------------------------------------------------------
extern "C" void kernel_launch(void* const* d_in, const int* in_sizes, int n_in,
                              void* d_out, int out_size)
{
    const float* dists = (const float*)d_in[0];
    const float* emb_e = (const float*)d_in[1];
    const float* emb_n = (const float*)d_in[2];
    const float* w1    = (const float*)d_in[3];
    const float* b1    = (const float*)d_in[4];
    const float* w2    = (const float*)d_in[5];
    const float* b2    = (const float*)d_in[6];
    const float* win   = (const float*)d_in[7];
    const float* wo1   = (const float*)d_in[8];
    const float* bo1   = (const float*)d_in[9];
    const float* wo2   = (const float*)d_in[10];
    const float* bo2   = (const float*)d_in[11];
    float* out = (float*)d_out;

    float *xs, *zsv, *zv, *h2;
    cudaGetSymbolAddress((void**)&xs,  g_xs);
    cudaGetSymbolAddress((void**)&zsv, g_zs);
    cudaGetSymbolAddress((void**)&zv,  g_z);
    cudaGetSymbolAddress((void**)&h2,  g_h2);

    init_xs_kernel<<<(BATCH * NELEC * EDIM + 255) / 256, 256>>>(emb_e, xs);
    init_zsnuc_kernel<<<(BATCH * NNUC * KDIM + 255) / 256, 256>>>(emb_n, zsv);

    for (int t = 0; t < 3; t++) {
        linear_kernel<false, false, false><<<BATCH, 256>>>(
            xs, win + t * KDIM * EDIM, nullptr, nullptr, zsv, NALL * KDIM);

        pairconv_mma_kernel<<<BATCH * 4, 288>>>(
            dists, w1 + t * HIDK * BASIS, b1 + t * HIDK,
            w2 + t * KDIM * HIDK, b2 + t * KDIM, zsv, zv);

        linear_kernel<true, true, false><<<BATCH, 256>>>(
            zv, wo1 + t * HIDO * KDIM, bo1 + t * HIDO, nullptr, h2, NELEC * KDIM);

        float* dst = (t == 2) ? out : xs;
        linear_kernel<true, false, true><<<BATCH, 256>>>(
            h2, wo2 + t * EDIM * HIDO, bo2 + t * EDIM, xs, dst, NELEC * EDIM);
    }
}

// round 8
// speedup vs baseline: 2.1958x; 1.0588x over previous
#include <cuda_runtime.h>
#include <cstdint>

#define BATCH  512
#define NELEC  32
#define NALL   36
#define NNUC   4
#define BASIS  32
#define KDIM   128
#define EDIM   128
#define HIDK   64
#define HIDO   128

// Scratch (device globals)
__device__ float g_xs[BATCH * NELEC * EDIM];
__device__ float g_zs[BATCH * NALL * KDIM];
__device__ float g_z [BATCH * NELEC * KDIM];

__device__ __forceinline__ float sspf(float x) {
    float e = __expf(-fabsf(x));
    float l = __logf(1.0f + e);
    return fmaxf(x, 0.0f) + l - 0.69314718055994530942f;
}

// ---------------- bf16 MMA helpers ----------------
__device__ __forceinline__ void mma_bf16(float* c, const unsigned* a, const unsigned* b) {
    asm volatile("mma.sync.aligned.m16n8k16.row.col.f32.bf16.bf16.f32 "
        "{%0,%1,%2,%3}, {%4,%5,%6,%7}, {%8,%9}, {%0,%1,%2,%3};"
        : "+f"(c[0]), "+f"(c[1]), "+f"(c[2]), "+f"(c[3])
        : "r"(a[0]), "r"(a[1]), "r"(a[2]), "r"(a[3]), "r"(b[0]), "r"(b[1]));
}
// bf16x3: c += (Ah+Al)*(Bh+Bl) approx (drop Al*Bl)
__device__ __forceinline__ void mma3(float* c, const unsigned* ah, const unsigned* al,
                                     const unsigned* bh, const unsigned* bl) {
    mma_bf16(c, ah, bh);
    mma_bf16(c, al, bh);
    mma_bf16(c, ah, bl);
}

__device__ __forceinline__ unsigned pack_bf16(float f0, float f1) {
    unsigned r;
    asm("cvt.rn.bf16x2.f32 %0, %1, %2;" : "=r"(r) : "f"(f1), "f"(f0));
    return r;
}
__device__ __forceinline__ void split2(float f0, float f1, unsigned &hi, unsigned &lo) {
    hi = pack_bf16(f0, f1);
    float h0 = __uint_as_float(hi << 16);
    float h1 = __uint_as_float(hi & 0xFFFF0000u);
    lo = pack_bf16(f0 - h0, f1 - h1);
}

__device__ __forceinline__ void ldm_x4(unsigned* r, const void* p) {
    unsigned a = (unsigned)__cvta_generic_to_shared(p);
    asm volatile("ldmatrix.sync.aligned.m8n8.x4.shared.b16 {%0,%1,%2,%3}, [%4];"
                 : "=r"(r[0]), "=r"(r[1]), "=r"(r[2]), "=r"(r[3]) : "r"(a));
}

// A-fragment (row-major M16K16) direct from gmem rows: a0=(r,c),(r,c+1); a1=r+8; a2=c+8; a3=r+8,c+8
__device__ __forceinline__ void afrag_ld(const float* base, int r, int c, int ld,
                                         unsigned* ah, unsigned* al) {
    float2 v00 = *(const float2*)&base[r * ld + c];
    float2 v10 = *(const float2*)&base[(r + 8) * ld + c];
    float2 v01 = *(const float2*)&base[r * ld + c + 8];
    float2 v11 = *(const float2*)&base[(r + 8) * ld + c + 8];
    split2(v00.x, v00.y, ah[0], al[0]);
    split2(v10.x, v10.y, ah[1], al[1]);
    split2(v01.x, v01.y, ah[2], al[2]);
    split2(v11.x, v11.y, ah[3], al[3]);
}

// B-fragment (K16N8, B[k][n]=W[n][k]) direct from gmem: lane L -> n=L/4, k pairs 2(L%4), +8
__device__ __forceinline__ void bfrag_ld(const float* W, int nrow, int kbase, int ld,
                                         unsigned* bh, unsigned* bl) {
    float2 w0 = *(const float2*)&W[nrow * ld + kbase];
    float2 w1 = *(const float2*)&W[nrow * ld + kbase + 8];
    split2(w0.x, w0.y, bh[0], bl[0]);
    split2(w1.x, w1.y, bh[1], bl[1]);
}

// ---------------------------------------------------------------------------
// init kernels
// ---------------------------------------------------------------------------
__global__ void init_xs_kernel(const float* __restrict__ emb_e, float* __restrict__ xs) {
    int idx = blockIdx.x * blockDim.x + threadIdx.x;
    if (idx < BATCH * NELEC * EDIM) xs[idx] = emb_e[idx & (NELEC * EDIM - 1)];
}

__global__ void init_zsnuc_kernel(const float* __restrict__ emb_n, float* __restrict__ zs) {
    int idx = blockIdx.x * blockDim.x + threadIdx.x;
    if (idx < BATCH * NNUC * KDIM) {
        int d = idx & 127;
        int m = (idx >> 7) & 3;
        int b = idx >> 9;
        zs[(b * NALL + NELEC + m) * KDIM + d] = emb_n[m * KDIM + d];
    }
}

// ---------------------------------------------------------------------------
// zs linear via MMA: zs[b,e,:] = xs[b,e,:] @ Win^T   (rows 0..31 of zs[b])
// Grid = BATCH, 256 threads (8 warps). Warp: 2 m-tiles x 2 n8-tiles, K=128.
// ---------------------------------------------------------------------------
__global__ __launch_bounds__(256) void zslin_mma_kernel(
    const float* __restrict__ in,   // (B,32,128)
    const float* __restrict__ W,    // (128,128)
    float* __restrict__ zs)         // (B,36,128)
{
    int b = blockIdx.x;
    int tid = threadIdx.x;
    int wid = tid >> 5, lane = tid & 31;
    int g = lane >> 2, t = lane & 3;
    int n0 = wid * 16;
    const float* inb = in + b * 4096;

    float c[2][2][4];
#pragma unroll
    for (int mi = 0; mi < 2; mi++)
#pragma unroll
        for (int nj = 0; nj < 2; nj++)
#pragma unroll
            for (int q = 0; q < 4; q++) c[mi][nj][q] = 0.f;

#pragma unroll
    for (int kt = 0; kt < 8; kt++) {
        unsigned ah[2][4], al[2][4];
#pragma unroll
        for (int mi = 0; mi < 2; mi++)
            afrag_ld(inb, mi * 16 + g, kt * 16 + 2 * t, 128, ah[mi], al[mi]);
#pragma unroll
        for (int nj = 0; nj < 2; nj++) {
            unsigned bh[2], bl[2];
            bfrag_ld(W, n0 + nj * 8 + g, kt * 16 + 2 * t, 128, bh, bl);
#pragma unroll
            for (int mi = 0; mi < 2; mi++)
                mma3(c[mi][nj], ah[mi], al[mi], bh, bl);
        }
    }

#pragma unroll
    for (int mi = 0; mi < 2; mi++)
#pragma unroll
        for (int nj = 0; nj < 2; nj++) {
            int r = mi * 16 + g;
            int k = n0 + nj * 8 + 2 * t;
            *(float2*)&zs[(b * NALL + r) * 128 + k] =
                make_float2(c[mi][nj][0], c[mi][nj][1]);
            *(float2*)&zs[(b * NALL + r + 8) * 128 + k] =
                make_float2(c[mi][nj][2], c[mi][nj][3]);
        }
}

// ---------------------------------------------------------------------------
// Fused out-MLP: out = xs + ssp(z@Wo1^T + bo1)@Wo2^T + bo2
// GEMM1 -> ssp -> bf16 split planes in smem -> ldmatrix A -> GEMM2.
// Grid = BATCH, 256 threads.
// ---------------------------------------------------------------------------
__global__ __launch_bounds__(256) void outmlp_mma_kernel(
    const float* __restrict__ z,    // (B,32,128)
    const float* __restrict__ wo1,  // (128,128)
    const float* __restrict__ bo1,  // (128)
    const float* __restrict__ wo2,  // (128,128)
    const float* __restrict__ bo2,  // (128)
    const float* __restrict__ xs,   // (B,32,128) residual
    float* __restrict__ out)        // (B,32,128)
{
    __shared__ unsigned short Hs[2][32][136];   // [plane][row][k], stride 68 words

    int b = blockIdx.x;
    int tid = threadIdx.x;
    int wid = tid >> 5, lane = tid & 31;
    int g = lane >> 2, t = lane & 3;
    int lr = lane & 7, lm = lane >> 3;
    int n0 = wid * 16;
    const float* inb = z + b * 4096;

    // ---- GEMM1 ----
    float c[2][2][4];
#pragma unroll
    for (int mi = 0; mi < 2; mi++)
#pragma unroll
        for (int nj = 0; nj < 2; nj++)
#pragma unroll
            for (int q = 0; q < 4; q++) c[mi][nj][q] = 0.f;

#pragma unroll
    for (int kt = 0; kt < 8; kt++) {
        unsigned ah[2][4], al[2][4];
#pragma unroll
        for (int mi = 0; mi < 2; mi++)
            afrag_ld(inb, mi * 16 + g, kt * 16 + 2 * t, 128, ah[mi], al[mi]);
#pragma unroll
        for (int nj = 0; nj < 2; nj++) {
            unsigned bh[2], bl[2];
            bfrag_ld(wo1, n0 + nj * 8 + g, kt * 16 + 2 * t, 128, bh, bl);
#pragma unroll
            for (int mi = 0; mi < 2; mi++)
                mma3(c[mi][nj], ah[mi], al[mi], bh, bl);
        }
    }

    // ---- epilogue 1: +bo1, ssp, split -> Hs planes ----
#pragma unroll
    for (int mi = 0; mi < 2; mi++)
#pragma unroll
        for (int nj = 0; nj < 2; nj++) {
            int r = mi * 16 + g;
            int k = n0 + nj * 8 + 2 * t;
            float2 bb = *(const float2*)&bo1[k];
            unsigned hi, lo;
            split2(sspf(c[mi][nj][0] + bb.x), sspf(c[mi][nj][1] + bb.y), hi, lo);
            *(unsigned*)&Hs[0][r][k] = hi;
            *(unsigned*)&Hs[1][r][k] = lo;
            split2(sspf(c[mi][nj][2] + bb.x), sspf(c[mi][nj][3] + bb.y), hi, lo);
            *(unsigned*)&Hs[0][r + 8][k] = hi;
            *(unsigned*)&Hs[1][r + 8][k] = lo;
        }
    __syncthreads();

    // ---- GEMM2: A = Hs via ldmatrix ----
    float d[2][2][4];
#pragma unroll
    for (int mi = 0; mi < 2; mi++)
#pragma unroll
        for (int nj = 0; nj < 2; nj++)
#pragma unroll
            for (int q = 0; q < 4; q++) d[mi][nj][q] = 0.f;

#pragma unroll
    for (int kt = 0; kt < 8; kt++) {
        unsigned ah[2][4], al[2][4];
#pragma unroll
        for (int mi = 0; mi < 2; mi++) {
            // matrices: (lm&1)-> row half, (lm>>1)-> k half
            const void* p0 = &Hs[0][mi * 16 + (lm & 1) * 8 + lr][kt * 16 + (lm >> 1) * 8];
            const void* p1 = &Hs[1][mi * 16 + (lm & 1) * 8 + lr][kt * 16 + (lm >> 1) * 8];
            ldm_x4(ah[mi], p0);
            ldm_x4(al[mi], p1);
        }
#pragma unroll
        for (int nj = 0; nj < 2; nj++) {
            unsigned bh[2], bl[2];
            bfrag_ld(wo2, n0 + nj * 8 + g, kt * 16 + 2 * t, 128, bh, bl);
#pragma unroll
            for (int mi = 0; mi < 2; mi++)
                mma3(d[mi][nj], ah[mi], al[mi], bh, bl);
        }
    }

    // ---- epilogue 2: +bo2 + residual ----
#pragma unroll
    for (int mi = 0; mi < 2; mi++)
#pragma unroll
        for (int nj = 0; nj < 2; nj++) {
            int r = mi * 16 + g;
            int k = n0 + nj * 8 + 2 * t;
            float2 bb = *(const float2*)&bo2[k];
            float2 r0 = *(const float2*)&xs[b * 4096 + r * 128 + k];
            float2 r1 = *(const float2*)&xs[b * 4096 + (r + 8) * 128 + k];
            *(float2*)&out[b * 4096 + r * 128 + k] =
                make_float2(d[mi][nj][0] + bb.x + r0.x, d[mi][nj][1] + bb.y + r0.y);
            *(float2*)&out[b * 4096 + (r + 8) * 128 + k] =
                make_float2(d[mi][nj][2] + bb.x + r1.x, d[mi][nj][3] + bb.y + r1.y);
        }
}

// ---------------------------------------------------------------------------
// Pair conv, mma.sync bf16x3 + ldmatrix (unchanged from R7 — verified fast path)
// ---------------------------------------------------------------------------
__global__ __launch_bounds__(288, 2) void pairconv_mma_kernel(
    const float* __restrict__ dists,   // (B,32,36,32)
    const float* __restrict__ w1,      // (64,32)
    const float* __restrict__ b1g,     // (64)
    const float* __restrict__ w2,      // (128,64)
    const float* __restrict__ b2g,     // (128)
    const float* __restrict__ zs,      // (B,36,128)
    float* __restrict__ z)             // (B,32,128)
{
    __shared__ unsigned short W1s[2][64][40];
    __shared__ unsigned short W2s[2][128][72];
    __shared__ float z_s[8][128];

    int tid = threadIdx.x;
    int b = blockIdx.x >> 2;
    int e0g = (blockIdx.x & 3) * 8;
    int wid = tid >> 5, lane = tid & 31;
    int g = lane >> 2, t = lane & 3;
    int lr = lane & 7, lm = lane >> 3;

    for (int idx = tid; idx < 64 * 16; idx += 288) {
        int n = idx >> 4, kp = idx & 15;
        unsigned hi, lo;
        split2(w1[n * 32 + 2 * kp], w1[n * 32 + 2 * kp + 1], hi, lo);
        *(unsigned*)&W1s[0][n][2 * kp] = hi;
        *(unsigned*)&W1s[1][n][2 * kp] = lo;
    }
    for (int idx = tid; idx < 128 * 32; idx += 288) {
        int n = idx >> 5, kp = idx & 31;
        unsigned hi, lo;
        split2(w2[n * 64 + 2 * kp], w2[n * 64 + 2 * kp + 1], hi, lo);
        *(unsigned*)&W2s[0][n][2 * kp] = hi;
        *(unsigned*)&W2s[1][n][2 * kp] = lo;
    }
    for (int idx = tid; idx < 1024; idx += 288) ((float*)z_s)[idx] = 0.f;
    __syncthreads();

    const float* drow = dists + ((long)(b * 32 + e0g) * 36) * 32;
    const float* zrow = zs + b * (36 * 128);

    int e_lo = (wid * 32) / 36;
    int e_hi = (wid * 32 + 31) / 36;

    unsigned a2h[2][4][4], a2l[2][4][4];
    int ja_[2], jb_[2];
    bool skip0_[2], skip1_[2];
    bool hi0_[2], hi1_[2];

#pragma unroll
    for (int i = 0; i < 2; i++) {
        int mb = wid * 32 + i * 16;
        int r0 = mb + g, r1 = r0 + 8;
        int ea = r0 / 36, ja = r0 - 36 * ea;
        int eb = r1 / 36, jb = r1 - 36 * eb;
        ja_[i] = ja; jb_[i] = jb;
        skip0_[i] = (ja == e0g + ea);
        skip1_[i] = (jb == e0g + eb);
        hi0_[i] = (ea != e_lo);
        hi1_[i] = (eb != e_lo);

        unsigned ah[2][4], al[2][4];
#pragma unroll
        for (int kt = 0; kt < 2; kt++) {
            int col = 16 * kt + 2 * t;
            float2 v00 = *(const float2*)&drow[(ea * 36 + ja) * 32 + col];
            float2 v10 = *(const float2*)&drow[(eb * 36 + jb) * 32 + col];
            float2 v01 = *(const float2*)&drow[(ea * 36 + ja) * 32 + col + 8];
            float2 v11 = *(const float2*)&drow[(eb * 36 + jb) * 32 + col + 8];
            split2(v00.x, v00.y, ah[kt][0], al[kt][0]);
            split2(v10.x, v10.y, ah[kt][1], al[kt][1]);
            split2(v01.x, v01.y, ah[kt][2], al[kt][2]);
            split2(v11.x, v11.y, ah[kt][3], al[kt][3]);
        }

        float c1[8][4];
#pragma unroll
        for (int nt = 0; nt < 8; nt++) {
            unsigned bh[4], bl[4];
            ldm_x4(bh, &W1s[0][nt * 8 + lr][8 * lm]);
            ldm_x4(bl, &W1s[1][nt * 8 + lr][8 * lm]);
            float cA[4] = {0.f, 0.f, 0.f, 0.f};
            float cB[4] = {0.f, 0.f, 0.f, 0.f};
            mma3(cA, ah[0], al[0], &bh[0], &bl[0]);
            mma3(cB, ah[1], al[1], &bh[2], &bl[2]);
#pragma unroll
            for (int q = 0; q < 4; q++) c1[nt][q] = cA[q] + cB[q];
        }

#pragma unroll
        for (int kt2 = 0; kt2 < 4; kt2++) {
            int n0 = 2 * kt2, n1 = n0 + 1;
            float2 bb0 = *(const float2*)&b1g[n0 * 8 + 2 * t];
            float2 bb1 = *(const float2*)&b1g[n1 * 8 + 2 * t];
            split2(sspf(c1[n0][0] + bb0.x), sspf(c1[n0][1] + bb0.y), a2h[i][kt2][0], a2l[i][kt2][0]);
            split2(sspf(c1[n0][2] + bb0.x), sspf(c1[n0][3] + bb0.y), a2h[i][kt2][1], a2l[i][kt2][1]);
            split2(sspf(c1[n1][0] + bb1.x), sspf(c1[n1][1] + bb1.y), a2h[i][kt2][2], a2l[i][kt2][2]);
            split2(sspf(c1[n1][2] + bb1.x), sspf(c1[n1][3] + bb1.y), a2h[i][kt2][3], a2l[i][kt2][3]);
        }
    }

#pragma unroll
    for (int half = 0; half < 2; half++) {
#pragma unroll
        for (int nt = 0; nt < 8; nt++) {
            int nn = half * 64 + nt * 8;
            int k0 = nn + 2 * t;

            unsigned h0[4], h1[4], l0[4], l1[4];
            ldm_x4(h0, &W2s[0][nn + lr][8 * lm]);
            ldm_x4(h1, &W2s[0][nn + lr][32 + 8 * lm]);
            ldm_x4(l0, &W2s[1][nn + lr][8 * lm]);
            ldm_x4(l1, &W2s[1][nn + lr][32 + 8 * lm]);
            float2 bb = *(const float2*)&b2g[k0];

            float acc0[2] = {0.f, 0.f};
            float acc1[2] = {0.f, 0.f};

#pragma unroll
            for (int i = 0; i < 2; i++) {
                float2 zj0 = skip0_[i] ? make_float2(0.f, 0.f)
                                       : *(const float2*)&zrow[ja_[i] * 128 + k0];
                float2 zj1 = skip1_[i] ? make_float2(0.f, 0.f)
                                       : *(const float2*)&zrow[jb_[i] * 128 + k0];

                float cA[4] = {0.f, 0.f, 0.f, 0.f};
                float cB[4] = {0.f, 0.f, 0.f, 0.f};
                mma3(cA, a2h[i][0], a2l[i][0], &h0[0], &l0[0]);
                mma3(cA, a2h[i][1], a2l[i][1], &h0[2], &l0[2]);
                mma3(cB, a2h[i][2], a2l[i][2], &h1[0], &l1[0]);
                mma3(cB, a2h[i][3], a2l[i][3], &h1[2], &l1[2]);

                float p0 = (cA[0] + cB[0] + bb.x) * zj0.x;
                float p1 = (cA[1] + cB[1] + bb.y) * zj0.y;
                float p2 = (cA[2] + cB[2] + bb.x) * zj1.x;
                float p3 = (cA[3] + cB[3] + bb.y) * zj1.y;
                if (hi0_[i]) { acc1[0] += p0; acc1[1] += p1; }
                else         { acc0[0] += p0; acc0[1] += p1; }
                if (hi1_[i]) { acc1[0] += p2; acc1[1] += p3; }
                else         { acc0[0] += p2; acc0[1] += p3; }
            }

#pragma unroll
            for (int q = 0; q < 2; q++) {
                float v = acc0[q];
                v += __shfl_down_sync(0xffffffffu, v, 16);
                v += __shfl_down_sync(0xffffffffu, v, 8);
                v += __shfl_down_sync(0xffffffffu, v, 4);
                float w = acc1[q];
                w += __shfl_down_sync(0xffffffffu, w, 16);
                w += __shfl_down_sync(0xffffffffu, w, 8);
                w += __shfl_down_sync(0xffffffffu, w, 4);
                if (lane < 4) {
                    int k = nn + 2 * lane + q;
                    atomicAdd(&z_s[e_lo][k], v);
                    if (e_hi != e_lo) atomicAdd(&z_s[e_hi][k], w);
                }
            }
        }
    }

    __syncthreads();
    for (int idx = tid; idx < 1024; idx += 288) {
        int e = idx >> 7, k = idx & 127;
        z[(((long)(b * 32 + e0g + e)) << 7) + k] = z_s[e][k];
    }
}

// ---------------------------------------------------------------------------
// launch
// ---------------------------------------------------------------------------
extern "C" void kernel_launch(void* const* d_in, const int* in_sizes, int n_in,
                              void* d_out, int out_size)
{
    const float* dists = (const float*)d_in[0];
    const float* emb_e = (const float*)d_in[1];
    const float* emb_n = (const float*)d_in[2];
    const float* w1    = (const float*)d_in[3];
    const float* b1    = (const float*)d_in[4];
    const float* w2    = (const float*)d_in[5];
    const float* b2    = (const float*)d_in[6];
    const float* win   = (const float*)d_in[7];
    const float* wo1   = (const float*)d_in[8];
    const float* bo1   = (const float*)d_in[9];
    const float* wo2   = (const float*)d_in[10];
    const float* bo2   = (const float*)d_in[11];
    float* out = (float*)d_out;

    float *xs, *zsv, *zv;
    cudaGetSymbolAddress((void**)&xs,  g_xs);
    cudaGetSymbolAddress((void**)&zsv, g_zs);
    cudaGetSymbolAddress((void**)&zv,  g_z);

    init_xs_kernel<<<(BATCH * NELEC * EDIM + 255) / 256, 256>>>(emb_e, xs);
    init_zsnuc_kernel<<<(BATCH * NNUC * KDIM + 255) / 256, 256>>>(emb_n, zsv);

    for (int t = 0; t < 3; t++) {
        zslin_mma_kernel<<<BATCH, 256>>>(xs, win + t * KDIM * EDIM, zsv);

        pairconv_mma_kernel<<<BATCH * 4, 288>>>(
            dists, w1 + t * HIDK * BASIS, b1 + t * HIDK,
            w2 + t * KDIM * HIDK, b2 + t * KDIM, zsv, zv);

        float* dst = (t == 2) ? out : xs;
        outmlp_mma_kernel<<<BATCH, 256>>>(
            zv, wo1 + t * HIDO * KDIM, bo1 + t * HIDO,
            wo2 + t * EDIM * HIDO, bo2 + t * EDIM, xs, dst);
    }
}

// round 10
// speedup vs baseline: 2.2583x; 1.0284x over previous
#include <cuda_runtime.h>
#include <cstdint>

#define BATCH  512
#define NELEC  32
#define NALL   36
#define NNUC   4
#define BASIS  32
#define KDIM   128
#define EDIM   128
#define HIDK   64
#define HIDO   128

// Scratch (device globals)
__device__ float g_xs[BATCH * NELEC * EDIM];
__device__ float g_zs[BATCH * NALL * KDIM];
__device__ float g_z [BATCH * NELEC * KDIM];

__device__ __forceinline__ float sspf(float x) {
    float e = __expf(-fabsf(x));
    float l = __logf(1.0f + e);
    return fmaxf(x, 0.0f) + l - 0.69314718055994530942f;
}

// ---------------- bf16 MMA helpers ----------------
__device__ __forceinline__ void mma_bf16(float* c, const unsigned* a, const unsigned* b) {
    asm volatile("mma.sync.aligned.m16n8k16.row.col.f32.bf16.bf16.f32 "
        "{%0,%1,%2,%3}, {%4,%5,%6,%7}, {%8,%9}, {%0,%1,%2,%3};"
        : "+f"(c[0]), "+f"(c[1]), "+f"(c[2]), "+f"(c[3])
        : "r"(a[0]), "r"(a[1]), "r"(a[2]), "r"(a[3]), "r"(b[0]), "r"(b[1]));
}
// bf16x3: c += (Ah+Al)*(Bh+Bl) approx (drop Al*Bl)
__device__ __forceinline__ void mma3(float* c, const unsigned* ah, const unsigned* al,
                                     const unsigned* bh, const unsigned* bl) {
    mma_bf16(c, ah, bh);
    mma_bf16(c, al, bh);
    mma_bf16(c, ah, bl);
}
__device__ __forceinline__ unsigned pack_bf16(float f0, float f1) {
    unsigned r;
    asm("cvt.rn.bf16x2.f32 %0, %1, %2;" : "=r"(r) : "f"(f1), "f"(f0));
    return r;
}
__device__ __forceinline__ void split2(float f0, float f1, unsigned &hi, unsigned &lo) {
    hi = pack_bf16(f0, f1);
    float h0 = __uint_as_float(hi << 16);
    float h1 = __uint_as_float(hi & 0xFFFF0000u);
    lo = pack_bf16(f0 - h0, f1 - h1);
}
__device__ __forceinline__ void ldm_x4(unsigned* r, const void* p) {
    unsigned a = (unsigned)__cvta_generic_to_shared(p);
    asm volatile("ldmatrix.sync.aligned.m8n8.x4.shared.b16 {%0,%1,%2,%3}, [%4];"
                 : "=r"(r[0]), "=r"(r[1]), "=r"(r[2]), "=r"(r[3]) : "r"(a));
}
__device__ __forceinline__ void afrag_ld(const float* base, int r, int c, int ld,
                                         unsigned* ah, unsigned* al) {
    float2 v00 = *(const float2*)&base[r * ld + c];
    float2 v10 = *(const float2*)&base[(r + 8) * ld + c];
    float2 v01 = *(const float2*)&base[r * ld + c + 8];
    float2 v11 = *(const float2*)&base[(r + 8) * ld + c + 8];
    split2(v00.x, v00.y, ah[0], al[0]);
    split2(v10.x, v10.y, ah[1], al[1]);
    split2(v01.x, v01.y, ah[2], al[2]);
    split2(v11.x, v11.y, ah[3], al[3]);
}
__device__ __forceinline__ void bfrag_ld(const float* W, int nrow, int kbase, int ld,
                                         unsigned* bh, unsigned* bl) {
    float2 w0 = *(const float2*)&W[nrow * ld + kbase];
    float2 w1 = *(const float2*)&W[nrow * ld + kbase + 8];
    split2(w0.x, w0.y, bh[0], bl[0]);
    split2(w1.x, w1.y, bh[1], bl[1]);
}

// ---------------------------------------------------------------------------
// init kernel (nuc rows of zs; elec rows written by zslin/outmlp GEMM3)
// ---------------------------------------------------------------------------
__global__ void init_zsnuc_kernel(const float* __restrict__ emb_n, float* __restrict__ zs) {
    int idx = blockIdx.x * blockDim.x + threadIdx.x;
    if (idx < BATCH * NNUC * KDIM) {
        int d = idx & 127;
        int m = (idx >> 7) & 3;
        int b = idx >> 9;
        zs[(b * NALL + NELEC + m) * KDIM + d] = emb_n[m * KDIM + d];
    }
}

// ---------------------------------------------------------------------------
// zs linear for t=0: zs[b,0:32,:] = emb_e @ Win^T  (xs at t=0 is emb broadcast)
// ---------------------------------------------------------------------------
__global__ __launch_bounds__(256) void zslin_first_kernel(
    const float* __restrict__ emb_e,   // (32,128)
    const float* __restrict__ W,       // (128,128)
    float* __restrict__ zs)            // (B,36,128)
{
    int b = blockIdx.x;
    int tid = threadIdx.x;
    int wid = tid >> 5, lane = tid & 31;
    int g = lane >> 2, t = lane & 3;
    int n0 = wid * 16;

    float c[2][2][4];
#pragma unroll
    for (int mi = 0; mi < 2; mi++)
#pragma unroll
        for (int nj = 0; nj < 2; nj++)
#pragma unroll
            for (int q = 0; q < 4; q++) c[mi][nj][q] = 0.f;

#pragma unroll
    for (int kt = 0; kt < 8; kt++) {
        unsigned ah[2][4], al[2][4];
#pragma unroll
        for (int mi = 0; mi < 2; mi++)
            afrag_ld(emb_e, mi * 16 + g, kt * 16 + 2 * t, 128, ah[mi], al[mi]);
#pragma unroll
        for (int nj = 0; nj < 2; nj++) {
            unsigned bh[2], bl[2];
            bfrag_ld(W, n0 + nj * 8 + g, kt * 16 + 2 * t, 128, bh, bl);
#pragma unroll
            for (int mi = 0; mi < 2; mi++)
                mma3(c[mi][nj], ah[mi], al[mi], bh, bl);
        }
    }
#pragma unroll
    for (int mi = 0; mi < 2; mi++)
#pragma unroll
        for (int nj = 0; nj < 2; nj++) {
            int r = mi * 16 + g;
            int k = n0 + nj * 8 + 2 * t;
            *(float2*)&zs[(b * NALL + r) * 128 + k] = make_float2(c[mi][nj][0], c[mi][nj][1]);
            *(float2*)&zs[(b * NALL + r + 8) * 128 + k] = make_float2(c[mi][nj][2], c[mi][nj][3]);
        }
}

// ---------------------------------------------------------------------------
// Fused out-MLP (+ optional next-iteration zs linear):
//   xs_new = res + ssp(z@Wo1^T + bo1)@Wo2^T + bo2        -> out
//   if WRITE_ZS: zs[b,0:32,:] = xs_new @ Win_next^T      -> zs
// FIRST: residual read from emb_e (no batch offset).
// Smem plane buffer reused Hs -> Xs with sync guards.
// ---------------------------------------------------------------------------
template <bool FIRST, bool WRITE_ZS>
__global__ __launch_bounds__(256) void outmlp_mma_kernel(
    const float* __restrict__ z, const float* __restrict__ wo1,
    const float* __restrict__ bo1, const float* __restrict__ wo2,
    const float* __restrict__ bo2, const float* __restrict__ res,
    float* __restrict__ out,
    const float* __restrict__ win_next, float* __restrict__ zs)
{
    __shared__ unsigned short Hs[2][32][136];

    int b = blockIdx.x;
    int tid = threadIdx.x;
    int wid = tid >> 5, lane = tid & 31;
    int g = lane >> 2, t = lane & 3;
    int lr = lane & 7, lm = lane >> 3;
    int n0 = wid * 16;
    const float* inb = z + b * 4096;

    // ---- GEMM1: z @ Wo1^T ----
    float c[2][2][4];
#pragma unroll
    for (int mi = 0; mi < 2; mi++)
#pragma unroll
        for (int nj = 0; nj < 2; nj++)
#pragma unroll
            for (int q = 0; q < 4; q++) c[mi][nj][q] = 0.f;

#pragma unroll
    for (int kt = 0; kt < 8; kt++) {
        unsigned ah[2][4], al[2][4];
#pragma unroll
        for (int mi = 0; mi < 2; mi++)
            afrag_ld(inb, mi * 16 + g, kt * 16 + 2 * t, 128, ah[mi], al[mi]);
#pragma unroll
        for (int nj = 0; nj < 2; nj++) {
            unsigned bh[2], bl[2];
            bfrag_ld(wo1, n0 + nj * 8 + g, kt * 16 + 2 * t, 128, bh, bl);
#pragma unroll
            for (int mi = 0; mi < 2; mi++)
                mma3(c[mi][nj], ah[mi], al[mi], bh, bl);
        }
    }

    // ---- epi1: +bo1, ssp, split -> Hs ----
#pragma unroll
    for (int mi = 0; mi < 2; mi++)
#pragma unroll
        for (int nj = 0; nj < 2; nj++) {
            int r = mi * 16 + g;
            int k = n0 + nj * 8 + 2 * t;
            float2 bb = *(const float2*)&bo1[k];
            unsigned hi, lo;
            split2(sspf(c[mi][nj][0] + bb.x), sspf(c[mi][nj][1] + bb.y), hi, lo);
            *(unsigned*)&Hs[0][r][k] = hi;
            *(unsigned*)&Hs[1][r][k] = lo;
            split2(sspf(c[mi][nj][2] + bb.x), sspf(c[mi][nj][3] + bb.y), hi, lo);
            *(unsigned*)&Hs[0][r + 8][k] = hi;
            *(unsigned*)&Hs[1][r + 8][k] = lo;
        }
    __syncthreads();

    // ---- GEMM2: h @ Wo2^T ----
    float d[2][2][4];
#pragma unroll
    for (int mi = 0; mi < 2; mi++)
#pragma unroll
        for (int nj = 0; nj < 2; nj++)
#pragma unroll
            for (int q = 0; q < 4; q++) d[mi][nj][q] = 0.f;

#pragma unroll
    for (int kt = 0; kt < 8; kt++) {
        unsigned ah[2][4], al[2][4];
#pragma unroll
        for (int mi = 0; mi < 2; mi++) {
            const void* p0 = &Hs[0][mi * 16 + (lm & 1) * 8 + lr][kt * 16 + (lm >> 1) * 8];
            const void* p1 = &Hs[1][mi * 16 + (lm & 1) * 8 + lr][kt * 16 + (lm >> 1) * 8];
            ldm_x4(ah[mi], p0);
            ldm_x4(al[mi], p1);
        }
#pragma unroll
        for (int nj = 0; nj < 2; nj++) {
            unsigned bh[2], bl[2];
            bfrag_ld(wo2, n0 + nj * 8 + g, kt * 16 + 2 * t, 128, bh, bl);
#pragma unroll
            for (int mi = 0; mi < 2; mi++)
                mma3(d[mi][nj], ah[mi], al[mi], bh, bl);
        }
    }

    if (WRITE_ZS) __syncthreads();   // all Hs reads done before plane reuse

    // ---- epi2: +bo2 + residual -> out (and Xs planes if fusing zs) ----
#pragma unroll
    for (int mi = 0; mi < 2; mi++)
#pragma unroll
        for (int nj = 0; nj < 2; nj++) {
            int r = mi * 16 + g;
            int k = n0 + nj * 8 + 2 * t;
            float2 bb = *(const float2*)&bo2[k];
            long base0 = FIRST ? (long)(r * 128 + k) : (long)b * 4096 + r * 128 + k;
            long base1 = FIRST ? (long)((r + 8) * 128 + k) : (long)b * 4096 + (r + 8) * 128 + k;
            float2 r0 = *(const float2*)&res[base0];
            float2 r1 = *(const float2*)&res[base1];
            float v0 = d[mi][nj][0] + bb.x + r0.x;
            float v1 = d[mi][nj][1] + bb.y + r0.y;
            float v2 = d[mi][nj][2] + bb.x + r1.x;
            float v3 = d[mi][nj][3] + bb.y + r1.y;
            *(float2*)&out[(long)b * 4096 + r * 128 + k] = make_float2(v0, v1);
            *(float2*)&out[(long)b * 4096 + (r + 8) * 128 + k] = make_float2(v2, v3);
            if (WRITE_ZS) {
                unsigned hi, lo;
                split2(v0, v1, hi, lo);
                *(unsigned*)&Hs[0][r][k] = hi;
                *(unsigned*)&Hs[1][r][k] = lo;
                split2(v2, v3, hi, lo);
                *(unsigned*)&Hs[0][r + 8][k] = hi;
                *(unsigned*)&Hs[1][r + 8][k] = lo;
            }
        }

    if (WRITE_ZS) {
        __syncthreads();

        // ---- GEMM3: xs_new @ Win_next^T -> zs rows 0..31 ----
        float e[2][2][4];
#pragma unroll
        for (int mi = 0; mi < 2; mi++)
#pragma unroll
            for (int nj = 0; nj < 2; nj++)
#pragma unroll
                for (int q = 0; q < 4; q++) e[mi][nj][q] = 0.f;

#pragma unroll
        for (int kt = 0; kt < 8; kt++) {
            unsigned ah[2][4], al[2][4];
#pragma unroll
            for (int mi = 0; mi < 2; mi++) {
                const void* p0 = &Hs[0][mi * 16 + (lm & 1) * 8 + lr][kt * 16 + (lm >> 1) * 8];
                const void* p1 = &Hs[1][mi * 16 + (lm & 1) * 8 + lr][kt * 16 + (lm >> 1) * 8];
                ldm_x4(ah[mi], p0);
                ldm_x4(al[mi], p1);
            }
#pragma unroll
            for (int nj = 0; nj < 2; nj++) {
                unsigned bh[2], bl[2];
                bfrag_ld(win_next, n0 + nj * 8 + g, kt * 16 + 2 * t, 128, bh, bl);
#pragma unroll
                for (int mi = 0; mi < 2; mi++)
                    mma3(e[mi][nj], ah[mi], al[mi], bh, bl);
            }
        }

#pragma unroll
        for (int mi = 0; mi < 2; mi++)
#pragma unroll
            for (int nj = 0; nj < 2; nj++) {
                int r = mi * 16 + g;
                int k = n0 + nj * 8 + 2 * t;
                *(float2*)&zs[(b * NALL + r) * 128 + k] =
                    make_float2(e[mi][nj][0], e[mi][nj][1]);
                *(float2*)&zs[(b * NALL + r + 8) * 128 + k] =
                    make_float2(e[mi][nj][2], e[mi][nj][3]);
            }
    }
}

// ---------------------------------------------------------------------------
// Pair conv, mma.sync bf16x3 + ldmatrix (verbatim from R7/R8 — verified 211us)
// ---------------------------------------------------------------------------
__global__ __launch_bounds__(288, 2) void pairconv_mma_kernel(
    const float* __restrict__ dists,   // (B,32,36,32)
    const float* __restrict__ w1,      // (64,32)
    const float* __restrict__ b1g,     // (64)
    const float* __restrict__ w2,      // (128,64)
    const float* __restrict__ b2g,     // (128)
    const float* __restrict__ zs,      // (B,36,128)
    float* __restrict__ z)             // (B,32,128)
{
    __shared__ unsigned short W1s[2][64][40];
    __shared__ unsigned short W2s[2][128][72];
    __shared__ float z_s[8][128];

    int tid = threadIdx.x;
    int b = blockIdx.x >> 2;
    int e0g = (blockIdx.x & 3) * 8;
    int wid = tid >> 5, lane = tid & 31;
    int g = lane >> 2, t = lane & 3;
    int lr = lane & 7, lm = lane >> 3;

    for (int idx = tid; idx < 64 * 16; idx += 288) {
        int n = idx >> 4, kp = idx & 15;
        unsigned hi, lo;
        split2(w1[n * 32 + 2 * kp], w1[n * 32 + 2 * kp + 1], hi, lo);
        *(unsigned*)&W1s[0][n][2 * kp] = hi;
        *(unsigned*)&W1s[1][n][2 * kp] = lo;
    }
    for (int idx = tid; idx < 128 * 32; idx += 288) {
        int n = idx >> 5, kp = idx & 31;
        unsigned hi, lo;
        split2(w2[n * 64 + 2 * kp], w2[n * 64 + 2 * kp + 1], hi, lo);
        *(unsigned*)&W2s[0][n][2 * kp] = hi;
        *(unsigned*)&W2s[1][n][2 * kp] = lo;
    }
    for (int idx = tid; idx < 1024; idx += 288) ((float*)z_s)[idx] = 0.f;
    __syncthreads();

    const float* drow = dists + ((long)(b * 32 + e0g) * 36) * 32;
    const float* zrow = zs + b * (36 * 128);

    int e_lo = (wid * 32) / 36;
    int e_hi = (wid * 32 + 31) / 36;

    unsigned a2h[2][4][4], a2l[2][4][4];
    int ja_[2], jb_[2];
    bool skip0_[2], skip1_[2];
    bool hi0_[2], hi1_[2];

#pragma unroll
    for (int i = 0; i < 2; i++) {
        int mb = wid * 32 + i * 16;
        int r0 = mb + g, r1 = r0 + 8;
        int ea = r0 / 36, ja = r0 - 36 * ea;
        int eb = r1 / 36, jb = r1 - 36 * eb;
        ja_[i] = ja; jb_[i] = jb;
        skip0_[i] = (ja == e0g + ea);
        skip1_[i] = (jb == e0g + eb);
        hi0_[i] = (ea != e_lo);
        hi1_[i] = (eb != e_lo);

        unsigned ah[2][4], al[2][4];
#pragma unroll
        for (int kt = 0; kt < 2; kt++) {
            int col = 16 * kt + 2 * t;
            float2 v00 = *(const float2*)&drow[(ea * 36 + ja) * 32 + col];
            float2 v10 = *(const float2*)&drow[(eb * 36 + jb) * 32 + col];
            float2 v01 = *(const float2*)&drow[(ea * 36 + ja) * 32 + col + 8];
            float2 v11 = *(const float2*)&drow[(eb * 36 + jb) * 32 + col + 8];
            split2(v00.x, v00.y, ah[kt][0], al[kt][0]);
            split2(v10.x, v10.y, ah[kt][1], al[kt][1]);
            split2(v01.x, v01.y, ah[kt][2], al[kt][2]);
            split2(v11.x, v11.y, ah[kt][3], al[kt][3]);
        }

        float c1[8][4];
#pragma unroll
        for (int nt = 0; nt < 8; nt++) {
            unsigned bh[4], bl[4];
            ldm_x4(bh, &W1s[0][nt * 8 + lr][8 * lm]);
            ldm_x4(bl, &W1s[1][nt * 8 + lr][8 * lm]);
            float cA[4] = {0.f, 0.f, 0.f, 0.f};
            float cB[4] = {0.f, 0.f, 0.f, 0.f};
            mma3(cA, ah[0], al[0], &bh[0], &bl[0]);
            mma3(cB, ah[1], al[1], &bh[2], &bl[2]);
#pragma unroll
            for (int q = 0; q < 4; q++) c1[nt][q] = cA[q] + cB[q];
        }

#pragma unroll
        for (int kt2 = 0; kt2 < 4; kt2++) {
            int n0 = 2 * kt2, n1 = n0 + 1;
            float2 bb0 = *(const float2*)&b1g[n0 * 8 + 2 * t];
            float2 bb1 = *(const float2*)&b1g[n1 * 8 + 2 * t];
            split2(sspf(c1[n0][0] + bb0.x), sspf(c1[n0][1] + bb0.y), a2h[i][kt2][0], a2l[i][kt2][0]);
            split2(sspf(c1[n0][2] + bb0.x), sspf(c1[n0][3] + bb0.y), a2h[i][kt2][1], a2l[i][kt2][1]);
            split2(sspf(c1[n1][0] + bb1.x), sspf(c1[n1][1] + bb1.y), a2h[i][kt2][2], a2l[i][kt2][2]);
            split2(sspf(c1[n1][2] + bb1.x), sspf(c1[n1][3] + bb1.y), a2h[i][kt2][3], a2l[i][kt2][3]);
        }
    }

#pragma unroll
    for (int half = 0; half < 2; half++) {
#pragma unroll
        for (int nt = 0; nt < 8; nt++) {
            int nn = half * 64 + nt * 8;
            int k0 = nn + 2 * t;

            unsigned h0[4], h1[4], l0[4], l1[4];
            ldm_x4(h0, &W2s[0][nn + lr][8 * lm]);
            ldm_x4(h1, &W2s[0][nn + lr][32 + 8 * lm]);
            ldm_x4(l0, &W2s[1][nn + lr][8 * lm]);
            ldm_x4(l1, &W2s[1][nn + lr][32 + 8 * lm]);
            float2 bb = *(const float2*)&b2g[k0];

            float acc0[2] = {0.f, 0.f};
            float acc1[2] = {0.f, 0.f};

#pragma unroll
            for (int i = 0; i < 2; i++) {
                float2 zj0 = skip0_[i] ? make_float2(0.f, 0.f)
                                       : *(const float2*)&zrow[ja_[i] * 128 + k0];
                float2 zj1 = skip1_[i] ? make_float2(0.f, 0.f)
                                       : *(const float2*)&zrow[jb_[i] * 128 + k0];

                float cA[4] = {0.f, 0.f, 0.f, 0.f};
                float cB[4] = {0.f, 0.f, 0.f, 0.f};
                mma3(cA, a2h[i][0], a2l[i][0], &h0[0], &l0[0]);
                mma3(cA, a2h[i][1], a2l[i][1], &h0[2], &l0[2]);
                mma3(cB, a2h[i][2], a2l[i][2], &h1[0], &l1[0]);
                mma3(cB, a2h[i][3], a2l[i][3], &h1[2], &l1[2]);

                float p0 = (cA[0] + cB[0] + bb.x) * zj0.x;
                float p1 = (cA[1] + cB[1] + bb.y) * zj0.y;
                float p2 = (cA[2] + cB[2] + bb.x) * zj1.x;
                float p3 = (cA[3] + cB[3] + bb.y) * zj1.y;
                if (hi0_[i]) { acc1[0] += p0; acc1[1] += p1; }
                else         { acc0[0] += p0; acc0[1] += p1; }
                if (hi1_[i]) { acc1[0] += p2; acc1[1] += p3; }
                else         { acc0[0] += p2; acc0[1] += p3; }
            }

#pragma unroll
            for (int q = 0; q < 2; q++) {
                float v = acc0[q];
                v += __shfl_down_sync(0xffffffffu, v, 16);
                v += __shfl_down_sync(0xffffffffu, v, 8);
                v += __shfl_down_sync(0xffffffffu, v, 4);
                float w = acc1[q];
                w += __shfl_down_sync(0xffffffffu, w, 16);
                w += __shfl_down_sync(0xffffffffu, w, 8);
                w += __shfl_down_sync(0xffffffffu, w, 4);
                if (lane < 4) {
                    int k = nn + 2 * lane + q;
                    atomicAdd(&z_s[e_lo][k], v);
                    if (e_hi != e_lo) atomicAdd(&z_s[e_hi][k], w);
                }
            }
        }
    }

    __syncthreads();
    for (int idx = tid; idx < 1024; idx += 288) {
        int e = idx >> 7, k = idx & 127;
        z[(((long)(b * 32 + e0g + e)) << 7) + k] = z_s[e][k];
    }
}

// ---------------------------------------------------------------------------
// launch
// ---------------------------------------------------------------------------
extern "C" void kernel_launch(void* const* d_in, const int* in_sizes, int n_in,
                              void* d_out, int out_size)
{
    const float* dists = (const float*)d_in[0];
    const float* emb_e = (const float*)d_in[1];
    const float* emb_n = (const float*)d_in[2];
    const float* w1    = (const float*)d_in[3];
    const float* b1    = (const float*)d_in[4];
    const float* w2    = (const float*)d_in[5];
    const float* b2    = (const float*)d_in[6];
    const float* win   = (const float*)d_in[7];
    const float* wo1   = (const float*)d_in[8];
    const float* bo1   = (const float*)d_in[9];
    const float* wo2   = (const float*)d_in[10];
    const float* bo2   = (const float*)d_in[11];
    float* out = (float*)d_out;

    float *xs, *zsv, *zv;
    cudaGetSymbolAddress((void**)&xs,  g_xs);
    cudaGetSymbolAddress((void**)&zsv, g_zs);
    cudaGetSymbolAddress((void**)&zv,  g_z);

    init_zsnuc_kernel<<<(BATCH * NNUC * KDIM + 255) / 256, 256>>>(emb_n, zsv);

    // t=0 zs linear (xs == emb broadcast)
    zslin_first_kernel<<<BATCH, 256>>>(emb_e, win, zsv);

    // t = 0: residual from emb_e, fuse zs(t=1)
    pairconv_mma_kernel<<<BATCH * 4, 288>>>(
        dists, w1, b1, w2, b2, zsv, zv);
    outmlp_mma_kernel<true, true><<<BATCH, 256>>>(
        zv, wo1, bo1, wo2, bo2, emb_e, xs,
        win + 1 * KDIM * EDIM, zsv);

    // t = 1: fuse zs(t=2)
    pairconv_mma_kernel<<<BATCH * 4, 288>>>(
        dists, w1 + 1 * HIDK * BASIS, b1 + 1 * HIDK,
        w2 + 1 * KDIM * HIDK, b2 + 1 * KDIM, zsv, zv);
    outmlp_mma_kernel<false, true><<<BATCH, 256>>>(
        zv, wo1 + 1 * HIDO * KDIM, bo1 + 1 * HIDO,
        wo2 + 1 * EDIM * HIDO, bo2 + 1 * EDIM, xs, xs,
        win + 2 * KDIM * EDIM, zsv);

    // t = 2: final, write d_out
    pairconv_mma_kernel<<<BATCH * 4, 288>>>(
        dists, w1 + 2 * HIDK * BASIS, b1 + 2 * HIDK,
        w2 + 2 * KDIM * HIDK, b2 + 2 * KDIM, zsv, zv);
    outmlp_mma_kernel<false, false><<<BATCH, 256>>>(
        zv, wo1 + 2 * HIDO * KDIM, bo1 + 2 * HIDO,
        wo2 + 2 * EDIM * HIDO, bo2 + 2 * EDIM, xs, out,
        nullptr, nullptr);
}